// round 3
// baseline (speedup 1.0000x reference)
#include <cuda_runtime.h>

typedef unsigned long long ull_t;

// ---------- packed fp32x2 helpers (Blackwell FFMA2, PTX-only) ----------
__device__ __forceinline__ ull_t pk2(float x, float y){
    ull_t r; asm("mov.b64 %0, {%1,%2};" : "=l"(r) : "f"(x), "f"(y)); return r;
}
__device__ __forceinline__ void fma2(ull_t &d, ull_t a, ull_t b){
    asm("fma.rn.f32x2 %0, %1, %2, %0;" : "+l"(d) : "l"(a), "l"(b));
}
__device__ __forceinline__ float2 upk2(ull_t v){
    float lo, hi; asm("mov.b64 {%0,%1}, %2;" : "=f"(lo), "=f"(hi) : "l"(v));
    return make_float2(lo, hi);
}
__device__ __forceinline__ float elup1(float x){ return x > 0.f ? x + 1.f : __expf(x); }

#define FMA8x4(ACCROW, AV, B01, B23) do { ull_t ad_ = pk2((AV),(AV)); \
    fma2((ACCROW)[0], ad_, (B01).x); fma2((ACCROW)[1], ad_, (B01).y); \
    fma2((ACCROW)[2], ad_, (B23).x); fma2((ACCROW)[3], ad_, (B23).y); } while(0)

// ---------- dims: B=4, S=8192, D=1024, H=8, dk=dv=128, SEG=512, nseg=16 ----------

// ---------- device scratch ----------
__device__ float g_Q[33554432];   // [32768][1024]
__device__ float g_K[33554432];
__device__ float g_V[33554432];
__device__ float g_P[8388608];    // [(b*8+h)*16+seg][128][128]
__device__ float g_Mem[8388608];  // inclusive prefix of g_P over seg
__device__ float g_Zseg[65536];   // [(b*8+h)*16+seg][128]
__device__ float g_Z[65536];

// =====================================================================
// K1: C[32768,1024] = X @ W + b   (BM=BN=128, BK=16, 256 thr, 8x8 tile)
// =====================================================================
__global__ __launch_bounds__(256) void k_proj(const float* __restrict__ X,
                                              const float* __restrict__ W,
                                              const float* __restrict__ bias,
                                              int which)
{
    float* __restrict__ C = (which == 0) ? g_Q : ((which == 1) ? g_K : g_V);
    __shared__ __align__(16) float As[16][128];   // [k][m]
    __shared__ __align__(16) float Bs[16][128];   // [k][n]
    const int tid = threadIdx.x, tx = tid & 15, ty = tid >> 4;
    const int row0 = blockIdx.y << 7, col0 = blockIdx.x << 7;
    const int ar = tid >> 2, ac4 = (tid & 3) << 2;
    const int br = tid >> 5, bc4 = (tid & 31) << 2;

    ull_t acc[8][4];
#pragma unroll
    for (int i = 0; i < 8; ++i)
#pragma unroll
        for (int j = 0; j < 4; ++j) acc[i][j] = 0ull;

    float4 pa0 = *(const float4*)(X + (size_t)(row0 + ar) * 1024 + ac4);
    float4 pa1 = *(const float4*)(X + (size_t)(row0 + ar + 64) * 1024 + ac4);
    float4 pb0 = *(const float4*)(W + (size_t)br * 1024 + col0 + bc4);
    float4 pb1 = *(const float4*)(W + (size_t)(br + 8) * 1024 + col0 + bc4);

    for (int t = 0; t < 64; ++t) {
        As[ac4 + 0][ar] = pa0.x; As[ac4 + 1][ar] = pa0.y;
        As[ac4 + 2][ar] = pa0.z; As[ac4 + 3][ar] = pa0.w;
        As[ac4 + 0][ar + 64] = pa1.x; As[ac4 + 1][ar + 64] = pa1.y;
        As[ac4 + 2][ar + 64] = pa1.z; As[ac4 + 3][ar + 64] = pa1.w;
        *(float4*)&Bs[br][bc4]     = pb0;
        *(float4*)&Bs[br + 8][bc4] = pb1;
        __syncthreads();
        if (t < 63) {
            const int k0 = (t + 1) << 4;
            pa0 = *(const float4*)(X + (size_t)(row0 + ar) * 1024 + k0 + ac4);
            pa1 = *(const float4*)(X + (size_t)(row0 + ar + 64) * 1024 + k0 + ac4);
            pb0 = *(const float4*)(W + (size_t)(k0 + br) * 1024 + col0 + bc4);
            pb1 = *(const float4*)(W + (size_t)(k0 + br + 8) * 1024 + col0 + bc4);
        }
#pragma unroll
        for (int kk = 0; kk < 16; ++kk) {
            float4 a0 = *(const float4*)&As[kk][ty * 8];
            float4 a1 = *(const float4*)&As[kk][ty * 8 + 4];
            ulonglong2 b01 = *(const ulonglong2*)&Bs[kk][tx * 8];
            ulonglong2 b23 = *(const ulonglong2*)&Bs[kk][tx * 8 + 4];
            FMA8x4(acc[0], a0.x, b01, b23);
            FMA8x4(acc[1], a0.y, b01, b23);
            FMA8x4(acc[2], a0.z, b01, b23);
            FMA8x4(acc[3], a0.w, b01, b23);
            FMA8x4(acc[4], a1.x, b01, b23);
            FMA8x4(acc[5], a1.y, b01, b23);
            FMA8x4(acc[6], a1.z, b01, b23);
            FMA8x4(acc[7], a1.w, b01, b23);
        }
        __syncthreads();
    }
#pragma unroll
    for (int i = 0; i < 8; ++i) {
        size_t rb = (size_t)(row0 + ty * 8 + i) * 1024 + col0 + tx * 8;
#pragma unroll
        for (int jp = 0; jp < 4; ++jp) {
            float2 v = upk2(acc[i][jp]);
            int c = col0 + tx * 8 + jp * 2;
            C[rb + jp * 2]     = v.x + bias[c];
            C[rb + jp * 2 + 1] = v.y + bias[c + 1];
        }
    }
}

// =====================================================================
// K2: per (b,h,seg): P = (elu(K)+1)^T @ V  [128x128], Zseg = 512*colsum
// =====================================================================
__global__ __launch_bounds__(256) void k_kvouter()
{
    const int idx = blockIdx.x;                  // b*128 + h*16 + seg
    const int b = idx >> 7, h = (idx >> 4) & 7, seg = idx & 15;
    __shared__ __align__(16) float sks[16][128];
    __shared__ __align__(16) float vvs[16][128];
    const int tid = threadIdx.x, tx = tid & 15, ty = tid >> 4;
    const int lr = tid >> 5, c4 = (tid & 31) << 2;

    ull_t acc[8][4];
#pragma unroll
    for (int i = 0; i < 8; ++i)
#pragma unroll
        for (int j = 0; j < 4; ++j) acc[i][j] = 0ull;
    float zacc[8] = {0.f,0.f,0.f,0.f,0.f,0.f,0.f,0.f};

    const size_t rowbase = (size_t)(b * 8192 + seg * 512) * 1024 + h * 128;

    for (int l0 = 0; l0 < 512; l0 += 16) {
        float4 k0v = *(const float4*)(g_K + rowbase + (size_t)(l0 + lr) * 1024 + c4);
        float4 k1v = *(const float4*)(g_K + rowbase + (size_t)(l0 + lr + 8) * 1024 + c4);
        float4 v0v = *(const float4*)(g_V + rowbase + (size_t)(l0 + lr) * 1024 + c4);
        float4 v1v = *(const float4*)(g_V + rowbase + (size_t)(l0 + lr + 8) * 1024 + c4);
        k0v.x = elup1(k0v.x); k0v.y = elup1(k0v.y); k0v.z = elup1(k0v.z); k0v.w = elup1(k0v.w);
        k1v.x = elup1(k1v.x); k1v.y = elup1(k1v.y); k1v.z = elup1(k1v.z); k1v.w = elup1(k1v.w);
        __syncthreads();
        *(float4*)&sks[lr][c4]     = k0v;
        *(float4*)&sks[lr + 8][c4] = k1v;
        *(float4*)&vvs[lr][c4]     = v0v;
        *(float4*)&vvs[lr + 8][c4] = v1v;
        __syncthreads();
#pragma unroll
        for (int l = 0; l < 16; ++l) {
            float4 a0 = *(const float4*)&sks[l][ty * 8];
            float4 a1 = *(const float4*)&sks[l][ty * 8 + 4];
            ulonglong2 b01 = *(const ulonglong2*)&vvs[l][tx * 8];
            ulonglong2 b23 = *(const ulonglong2*)&vvs[l][tx * 8 + 4];
            if (tx == 0) {
                zacc[0] += a0.x; zacc[1] += a0.y; zacc[2] += a0.z; zacc[3] += a0.w;
                zacc[4] += a1.x; zacc[5] += a1.y; zacc[6] += a1.z; zacc[7] += a1.w;
            }
            FMA8x4(acc[0], a0.x, b01, b23);
            FMA8x4(acc[1], a0.y, b01, b23);
            FMA8x4(acc[2], a0.z, b01, b23);
            FMA8x4(acc[3], a0.w, b01, b23);
            FMA8x4(acc[4], a1.x, b01, b23);
            FMA8x4(acc[5], a1.y, b01, b23);
            FMA8x4(acc[6], a1.z, b01, b23);
            FMA8x4(acc[7], a1.w, b01, b23);
        }
    }
    const size_t pbase = (size_t)idx * 16384;
#pragma unroll
    for (int i = 0; i < 8; ++i) {
        size_t rb = pbase + (size_t)(ty * 8 + i) * 128 + tx * 8;
#pragma unroll
        for (int jp = 0; jp < 4; ++jp) {
            float2 v = upk2(acc[i][jp]);
            g_P[rb + jp * 2]     = v.x;
            g_P[rb + jp * 2 + 1] = v.y;
        }
    }
    if (tx == 0) {
#pragma unroll
        for (int i = 0; i < 8; ++i)
            g_Zseg[idx * 128 + ty * 8 + i] = 512.f * zacc[i];
    }
}

// =====================================================================
// K3: inclusive prefix over seg (16 steps) for P -> Mem and Zseg -> Z
// =====================================================================
__global__ __launch_bounds__(256) void k_prefix()
{
    const int bh = blockIdx.x;       // b*8+h, 0..31
    const int tid = threadIdx.x;
    float acc[64];
#pragma unroll
    for (int u = 0; u < 64; ++u) acc[u] = 0.f;
    float zacc = 0.f;
    for (int seg = 0; seg < 16; ++seg) {
        const size_t base = ((size_t)bh * 16 + seg) * 16384;
#pragma unroll
        for (int u = 0; u < 64; ++u) {
            acc[u] += g_P[base + u * 256 + tid];
            g_Mem[base + u * 256 + tid] = acc[u];
        }
        if (tid < 128) {
            zacc += g_Zseg[(bh * 16 + seg) * 128 + tid];
            g_Z[(bh * 16 + seg) * 128 + tid] = zacc;
        }
    }
}

// =====================================================================
// K4: per (b,seg,qt64): loop 8 heads: softmax attn + linear retrieval,
//     head-mean beta blend. smem: Qs 32KB | KV 32KB | Sc 129KB | zs | rs
// =====================================================================
__global__ __launch_bounds__(256, 1) void k_attn(const float* __restrict__ beta,
                                                 float* __restrict__ out)
{
    extern __shared__ __align__(16) float sm[];
    float* Qs = sm;                       // [128k][64r]   = 8192
    float* KV = sm + 8192;                // [..][..]      = 8192
    float* Sc = sm + 16384;               // [64][516]     = 33024
    float* zs = sm + 49408;               // 128
    float* rs = sm + 49536;               // 64

    const int idx = blockIdx.x;           // b*128 + seg*8 + qt
    const int b = idx >> 7, seg = (idx >> 3) & 15, qt = idx & 7;
    const int tid = threadIdx.x, tx = tid & 15, ty = tid >> 4;
    const float bsig = 1.f / (1.f + __expf(-beta[0]));
    const float bsig8 = bsig * 0.125f, obsig8 = (1.f - bsig) * 0.125f;
    const float scale = 0.088388347648318447f;    // 1/sqrt(128)
    const int qrow0 = b * 8192 + seg * 512 + qt * 64;
    const int krow0 = b * 8192 + seg * 512;

    const int r4 = tid >> 2, p32 = (tid & 3) * 32;   // transposed loaders
    const float* QLsrc = g_Q + (size_t)(qrow0 + r4) * 1024 + p32;

    float facc[4][8];
#pragma unroll
    for (int i = 0; i < 4; ++i)
#pragma unroll
        for (int j = 0; j < 8; ++j) facc[i][j] = 0.f;

    for (int h = 0; h < 8; ++h) {
        const int hc = h * 128;
        __syncthreads();
        // load Q tile transposed Qs[k][r]; zs
#pragma unroll
        for (int u = 0; u < 8; ++u) {
            float4 v = *(const float4*)(QLsrc + hc + u * 4);
            Qs[(p32 + u * 4 + 0) * 64 + r4] = v.x;
            Qs[(p32 + u * 4 + 1) * 64 + r4] = v.y;
            Qs[(p32 + u * 4 + 2) * 64 + r4] = v.z;
            Qs[(p32 + u * 4 + 3) * 64 + r4] = v.w;
        }
        if (tid < 128)
            zs[tid] = g_Z[((size_t)(b * 8 + h) * 16 + seg) * 128 + tid];

        // ---- scores: Sc[r][key] = (Q K^T) * scale, chunks of 64 keys ----
        for (int kc = 0; kc < 8; ++kc) {
            float4 ld[8];
            const float* src = g_K + (size_t)(krow0 + kc * 64 + r4) * 1024 + hc + p32;
#pragma unroll
            for (int u = 0; u < 8; ++u) ld[u] = *(const float4*)(src + u * 4);
            __syncthreads();
#pragma unroll
            for (int u = 0; u < 8; ++u) {
                KV[(p32 + u * 4 + 0) * 64 + r4] = ld[u].x;
                KV[(p32 + u * 4 + 1) * 64 + r4] = ld[u].y;
                KV[(p32 + u * 4 + 2) * 64 + r4] = ld[u].z;
                KV[(p32 + u * 4 + 3) * 64 + r4] = ld[u].w;
            }
            __syncthreads();
            ull_t sacc[4][2];
#pragma unroll
            for (int i = 0; i < 4; ++i) { sacc[i][0] = 0ull; sacc[i][1] = 0ull; }
#pragma unroll 8
            for (int kk = 0; kk < 128; ++kk) {
                float4 a = *(const float4*)&Qs[kk * 64 + ty * 4];
                ulonglong2 bb = *(const ulonglong2*)&KV[kk * 64 + tx * 4];
                ull_t ad;
                ad = pk2(a.x, a.x); fma2(sacc[0][0], ad, bb.x); fma2(sacc[0][1], ad, bb.y);
                ad = pk2(a.y, a.y); fma2(sacc[1][0], ad, bb.x); fma2(sacc[1][1], ad, bb.y);
                ad = pk2(a.z, a.z); fma2(sacc[2][0], ad, bb.x); fma2(sacc[2][1], ad, bb.y);
                ad = pk2(a.w, a.w); fma2(sacc[3][0], ad, bb.x); fma2(sacc[3][1], ad, bb.y);
            }
#pragma unroll
            for (int i = 0; i < 4; ++i) {
                float* dst = &Sc[(ty * 4 + i) * 516 + kc * 64 + tx * 4];
                float2 v0 = upk2(sacc[i][0]), v1 = upk2(sacc[i][1]);
                dst[0] = v0.x * scale; dst[1] = v0.y * scale;
                dst[2] = v1.x * scale; dst[3] = v1.y * scale;
            }
        }
        __syncthreads();
        // elu(Q)+1 in place (raw Q no longer needed)
        for (int u = tid; u < 8192; u += 256) Qs[u] = elup1(Qs[u]);
        // softmax (exp only; row sums to rs)
        {
            const int row = tid >> 2, part = tid & 3;
            float* rowp = &Sc[row * 516 + part * 128];
            float m = -1e30f;
#pragma unroll 8
            for (int j = 0; j < 128; ++j) m = fmaxf(m, rowp[j]);
            m = fmaxf(m, __shfl_xor_sync(0xffffffffu, m, 1));
            m = fmaxf(m, __shfl_xor_sync(0xffffffffu, m, 2));
            float s = 0.f;
#pragma unroll 8
            for (int j = 0; j < 128; ++j) { float e = __expf(rowp[j] - m); rowp[j] = e; s += e; }
            s += __shfl_xor_sync(0xffffffffu, s, 1);
            s += __shfl_xor_sync(0xffffffffu, s, 2);
            if (part == 0) rs[row] = s;
        }
        __syncthreads();

        // ---- a_dot = exp(S) @ V (normalize later), chunks of 64 keys ----
        ull_t dacc[4][4];
#pragma unroll
        for (int i = 0; i < 4; ++i)
#pragma unroll
            for (int j = 0; j < 4; ++j) dacc[i][j] = 0ull;
        for (int kc = 0; kc < 8; ++kc) {
            float4 ld[8];
            const float* src = g_V + (size_t)(krow0 + kc * 64 + r4) * 1024 + hc + p32;
#pragma unroll
            for (int u = 0; u < 8; ++u) ld[u] = *(const float4*)(src + u * 4);
            __syncthreads();
#pragma unroll
            for (int u = 0; u < 8; ++u)
                *(float4*)&KV[r4 * 128 + p32 + u * 4] = ld[u];
            __syncthreads();
#pragma unroll 4
            for (int kk = 0; kk < 64; ++kk) {
                ulonglong2 b01 = *(const ulonglong2*)&KV[kk * 128 + tx * 8];
                ulonglong2 b23 = *(const ulonglong2*)&KV[kk * 128 + tx * 8 + 4];
                const float* ap = &Sc[(ty * 4) * 516 + kc * 64 + kk];
                FMA8x4(dacc[0], ap[0],     b01, b23);
                FMA8x4(dacc[1], ap[516],   b01, b23);
                FMA8x4(dacc[2], ap[1032],  b01, b23);
                FMA8x4(dacc[3], ap[1548],  b01, b23);
            }
        }

        // ---- retrieval: macc = sq @ mem, den = sq @ z ----
        ull_t macc[4][4];
#pragma unroll
        for (int i = 0; i < 4; ++i)
#pragma unroll
            for (int j = 0; j < 4; ++j) macc[i][j] = 0ull;
        float den[4] = {0.f, 0.f, 0.f, 0.f};
        const size_t membase = ((size_t)(b * 8 + h) * 16 + seg) * 16384;
        for (int mc = 0; mc < 2; ++mc) {
            float4 ld[8];
            const float* src = g_Mem + membase + (size_t)(mc * 64 + r4) * 128 + p32;
#pragma unroll
            for (int u = 0; u < 8; ++u) ld[u] = *(const float4*)(src + u * 4);
            __syncthreads();
#pragma unroll
            for (int u = 0; u < 8; ++u)
                *(float4*)&KV[r4 * 128 + p32 + u * 4] = ld[u];
            __syncthreads();
#pragma unroll 4
            for (int kk = 0; kk < 64; ++kk) {
                const int kg = mc * 64 + kk;
                ulonglong2 b01 = *(const ulonglong2*)&KV[kk * 128 + tx * 8];
                ulonglong2 b23 = *(const ulonglong2*)&KV[kk * 128 + tx * 8 + 4];
                const float zk = zs[kg];
                const float* ap = &Qs[kg * 64 + ty * 4];
                den[0] += ap[0] * zk; FMA8x4(macc[0], ap[0], b01, b23);
                den[1] += ap[1] * zk; FMA8x4(macc[1], ap[1], b01, b23);
                den[2] += ap[2] * zk; FMA8x4(macc[2], ap[2], b01, b23);
                den[3] += ap[3] * zk; FMA8x4(macc[3], ap[3], b01, b23);
            }
        }

        // ---- blend into persistent head-mean accumulator ----
#pragma unroll
        for (int i = 0; i < 4; ++i) {
            const float minv = bsig8 / (den[i] + 1e-5f);
            const float dinv = obsig8 / rs[ty * 4 + i];
#pragma unroll
            for (int jp = 0; jp < 4; ++jp) {
                float2 dv = upk2(dacc[i][jp]);
                float2 mv = upk2(macc[i][jp]);
                facc[i][jp * 2]     += mv.x * minv + dv.x * dinv;
                facc[i][jp * 2 + 1] += mv.y * minv + dv.y * dinv;
            }
        }
    }

#pragma unroll
    for (int i = 0; i < 4; ++i) {
        float* dst = out + (size_t)(qrow0 + ty * 4 + i) * 128 + tx * 8;
#pragma unroll
        for (int j = 0; j < 8; ++j) dst[j] = facc[i][j];
    }
}

// =====================================================================
extern "C" void kernel_launch(void* const* d_in, const int* in_sizes, int n_in,
                              void* d_out, int out_size)
{
    const float* x    = (const float*)d_in[0];
    const float* wq   = (const float*)d_in[1];
    const float* bq   = (const float*)d_in[2];
    const float* wk   = (const float*)d_in[3];
    const float* bk   = (const float*)d_in[4];
    const float* wv   = (const float*)d_in[5];
    const float* bv   = (const float*)d_in[6];
    const float* beta = (const float*)d_in[7];
    float* out = (float*)d_out;

    static int smem_set = 0;
    if (!smem_set) {
        cudaFuncSetAttribute(k_attn, cudaFuncAttributeMaxDynamicSharedMemorySize, 198400);
        smem_set = 1;
    }

    dim3 g1(8, 256);
    k_proj<<<g1, 256>>>(x, wq, bq, 0);
    k_proj<<<g1, 256>>>(x, wk, bk, 1);
    k_proj<<<g1, 256>>>(x, wv, bv, 2);
    k_kvouter<<<512, 256>>>();
    k_prefix<<<32, 256>>>();
    k_attn<<<512, 256, 198400>>>(beta, out);
}

// round 5
// speedup vs baseline: 1.3950x; 1.3950x over previous
#include <cuda_runtime.h>
#include <cuda_bf16.h>
#include <cstdint>

typedef unsigned long long ull_t;

// ---------- packed fp32x2 helpers (Blackwell FFMA2, PTX-only) ----------
__device__ __forceinline__ ull_t pk2(float x, float y){
    ull_t r; asm("mov.b64 %0, {%1,%2};" : "=l"(r) : "f"(x), "f"(y)); return r;
}
__device__ __forceinline__ void fma2(ull_t &d, ull_t a, ull_t b){
    asm("fma.rn.f32x2 %0, %1, %2, %0;" : "+l"(d) : "l"(a), "l"(b));
}
__device__ __forceinline__ float2 upk2(ull_t v){
    float lo, hi; asm("mov.b64 {%0,%1}, %2;" : "=f"(lo), "=f"(hi) : "l"(v));
    return make_float2(lo, hi);
}
__device__ __forceinline__ float elup1(float x){ return x > 0.f ? x + 1.f : __expf(x); }

#define FMA8x4(ACCROW, AV, B01, B23) do { ull_t ad_ = pk2((AV),(AV)); \
    fma2((ACCROW)[0], ad_, (B01).x); fma2((ACCROW)[1], ad_, (B01).y); \
    fma2((ACCROW)[2], ad_, (B23).x); fma2((ACCROW)[3], ad_, (B23).y); } while(0)

// ---------- warp MMA helpers (plain sm_80+ PTX, legal on target sm_103) ----------
__device__ __forceinline__ uint32_t smem_u32(const void* p){
    uint32_t a;
    asm("{ .reg .u64 t; cvta.to.shared.u64 t, %1; cvt.u32.u64 %0, t; }" : "=r"(a) : "l"(p));
    return a;
}
__device__ __forceinline__ void ldsm_x4(uint32_t &r0, uint32_t &r1, uint32_t &r2, uint32_t &r3, uint32_t addr){
    asm volatile("ldmatrix.sync.aligned.m8n8.x4.shared.b16 {%0,%1,%2,%3}, [%4];"
        : "=r"(r0), "=r"(r1), "=r"(r2), "=r"(r3) : "r"(addr));
}
__device__ __forceinline__ void ldsm_x2(uint32_t &r0, uint32_t &r1, uint32_t addr){
    asm volatile("ldmatrix.sync.aligned.m8n8.x2.shared.b16 {%0,%1}, [%2];"
        : "=r"(r0), "=r"(r1) : "r"(addr));
}
__device__ __forceinline__ void mma16816(float &c0, float &c1, float &c2, float &c3,
                                         uint32_t a0, uint32_t a1, uint32_t a2, uint32_t a3,
                                         uint32_t b0, uint32_t b1){
    asm volatile("mma.sync.aligned.m16n8k16.row.col.f32.bf16.bf16.f32 "
        "{%0,%1,%2,%3}, {%4,%5,%6,%7}, {%8,%9}, {%0,%1,%2,%3};"
        : "+f"(c0), "+f"(c1), "+f"(c2), "+f"(c3)
        : "r"(a0), "r"(a1), "r"(a2), "r"(a3), "r"(b0), "r"(b1));
}

// ---------- dims: B=4, S=8192, D=1024, H=8, dk=dv=128, SEG=512, nseg=16 ----------

// ---------- device scratch ----------
__device__ float g_Q[33554432];   // [32768][1024]
__device__ float g_K[33554432];
__device__ float g_V[33554432];
__device__ float g_P[8388608];    // [(b*8+h)*16+seg][128][128]
__device__ float g_Mem[8388608];
__device__ float g_Zseg[65536];
__device__ float g_Z[65536];
__device__ __nv_bfloat16 g_Xh[33554432];   // bf16 split of x
__device__ __nv_bfloat16 g_Xl[33554432];
__device__ __nv_bfloat16 g_Wth[3145728];   // W^T hi, [which][n][k]
__device__ __nv_bfloat16 g_Wtl[3145728];   // W^T lo

// =====================================================================
// S1: split X into bf16 hi/lo
// =====================================================================
__global__ __launch_bounds__(256) void k_splitX(const float* __restrict__ x)
{
    size_t i = ((size_t)blockIdx.x * 256 + threadIdx.x) * 4;
    float4 v = *(const float4*)(x + i);
    __nv_bfloat16 hx = __float2bfloat16_rn(v.x), hy = __float2bfloat16_rn(v.y);
    __nv_bfloat16 hz = __float2bfloat16_rn(v.z), hw = __float2bfloat16_rn(v.w);
    __nv_bfloat16 lx = __float2bfloat16_rn(v.x - __bfloat162float(hx));
    __nv_bfloat16 ly = __float2bfloat16_rn(v.y - __bfloat162float(hy));
    __nv_bfloat16 lz = __float2bfloat16_rn(v.z - __bfloat162float(hz));
    __nv_bfloat16 lw = __float2bfloat16_rn(v.w - __bfloat162float(hw));
    *(__nv_bfloat162*)(g_Xh + i)     = __halves2bfloat162(hx, hy);
    *(__nv_bfloat162*)(g_Xh + i + 2) = __halves2bfloat162(hz, hw);
    *(__nv_bfloat162*)(g_Xl + i)     = __halves2bfloat162(lx, ly);
    *(__nv_bfloat162*)(g_Xl + i + 2) = __halves2bfloat162(lz, lw);
}

// =====================================================================
// S2: transpose + split W[k][n] -> Wt[n][k] bf16 hi/lo
// =====================================================================
__global__ __launch_bounds__(256) void k_splitW(const float* __restrict__ w, int which)
{
    __shared__ float t[32][33];
    const int bx = blockIdx.x << 5, by = blockIdx.y << 5;   // bx: n, by: k
    const int tx = threadIdx.x & 31, ty = threadIdx.x >> 5; // ty 0..7
#pragma unroll
    for (int r = 0; r < 4; ++r)
        t[ty * 4 + r][tx] = w[(size_t)(by + ty * 4 + r) * 1024 + bx + tx];
    __syncthreads();
    __nv_bfloat16* Ht = g_Wth + (size_t)which * 1048576;
    __nv_bfloat16* Lt = g_Wtl + (size_t)which * 1048576;
#pragma unroll
    for (int r = 0; r < 4; ++r) {
        int n = bx + ty * 4 + r, k = by + tx;
        float val = t[tx][ty * 4 + r];
        __nv_bfloat16 h = __float2bfloat16_rn(val);
        __nv_bfloat16 l = __float2bfloat16_rn(val - __bfloat162float(h));
        Ht[(size_t)n * 1024 + k] = h;
        Lt[(size_t)n * 1024 + k] = l;
    }
}

// =====================================================================
// K1: bf16 mma.sync projection GEMM, split-bf16 3-pass (K_eff = 3072)
//     CTA 128x128, 8 warps (2x4), warp tile 64x32, K-chunk 64, dbl-buffered
// =====================================================================
__global__ __launch_bounds__(256, 1) void k_proj_mma(const float* __restrict__ bias, int which)
{
    extern __shared__ __align__(128) char sm_raw[];
    // A bufs: [2][128 rows][64 bf16], B bufs: [2][128 rows][64 bf16]
    char* smA = sm_raw;            // 2 * 16384
    char* smB = sm_raw + 32768;    // 2 * 16384
    const uint32_t baseA = smem_u32(smA);
    const uint32_t baseB = smem_u32(smB);

    float* __restrict__ C = (which == 0) ? g_Q : ((which == 1) ? g_K : g_V);
    const __nv_bfloat16* Wh = g_Wth + (size_t)which * 1048576;
    const __nv_bfloat16* Wl = g_Wtl + (size_t)which * 1048576;

    const int tid = threadIdx.x, lane = tid & 31, wid = tid >> 5;
    const int wm = (wid >> 2) * 64, wn = (wid & 3) * 32;
    const int row0 = blockIdx.y << 7, col0 = blockIdx.x << 7;

    // loader mapping: thread covers rows tid/8 + {0,32,64,96}, 16B unit col tid&7
    const int ldr = tid >> 3, ldc = tid & 7;

    // ldmatrix per-thread bases
    const int rowA = wm + (lane & 15);           // + mt*16
    const int rA7 = rowA & 7;
    const int unA = lane >> 4;                   // + ks*2
    const int rowB = wn + (lane & 7);            // + nt*8
    const int rB7 = lane & 7;
    const int unB = (lane >> 3) & 1;             // + ks*2

    float cf[4][4][4];
#pragma unroll
    for (int mt = 0; mt < 4; ++mt)
#pragma unroll
        for (int nt = 0; nt < 4; ++nt)
#pragma unroll
            for (int q = 0; q < 4; ++q) cf[mt][nt][q] = 0.f;

    uint4 pva[4], pvb[4];
    // prologue: load chunk 0 (pass 0: Xh, Wh; k0 = 0)
    {
        const __nv_bfloat16* As = g_Xh;
#pragma unroll
        for (int i = 0; i < 4; ++i) {
            int r = ldr + i * 32;
            pva[i] = *(const uint4*)(As + (size_t)(row0 + r) * 1024 + ldc * 8);
            pvb[i] = *(const uint4*)(Wh + (size_t)(col0 + r) * 1024 + ldc * 8);
        }
#pragma unroll
        for (int i = 0; i < 4; ++i) {
            int r = ldr + i * 32;
            uint32_t so = r * 128 + ((ldc ^ (r & 7)) << 4);
            *(uint4*)(smA + so) = pva[i];
            *(uint4*)(smB + so) = pvb[i];
        }
    }
    __syncthreads();

    for (int c = 0; c < 48; ++c) {
        const int buf = c & 1;
        // prefetch next chunk into regs
        if (c < 47) {
            const int cn = c + 1;
            const int p = cn >> 4, k0 = (cn & 15) << 6;
            const __nv_bfloat16* As = (p < 2) ? g_Xh : g_Xl;
            const __nv_bfloat16* Bs = (p == 1) ? Wl : Wh;
#pragma unroll
            for (int i = 0; i < 4; ++i) {
                int r = ldr + i * 32;
                pva[i] = *(const uint4*)(As + (size_t)(row0 + r) * 1024 + k0 + ldc * 8);
                pvb[i] = *(const uint4*)(Bs + (size_t)(col0 + r) * 1024 + k0 + ldc * 8);
            }
        }
        // compute from buf
        const uint32_t bA = baseA + buf * 16384;
        const uint32_t bB = baseB + buf * 16384;
#pragma unroll
        for (int ks = 0; ks < 4; ++ks) {
            uint32_t af[4][4];
            uint32_t bfr[4][2];
#pragma unroll
            for (int mt = 0; mt < 4; ++mt) {
                uint32_t addr = bA + (rowA + mt * 16) * 128 + ((((ks << 1) + unA) ^ rA7) << 4);
                ldsm_x4(af[mt][0], af[mt][1], af[mt][2], af[mt][3], addr);
            }
#pragma unroll
            for (int nt = 0; nt < 4; ++nt) {
                uint32_t addr = bB + (rowB + nt * 8) * 128 + ((((ks << 1) + unB) ^ rB7) << 4);
                ldsm_x2(bfr[nt][0], bfr[nt][1], addr);
            }
#pragma unroll
            for (int mt = 0; mt < 4; ++mt)
#pragma unroll
                for (int nt = 0; nt < 4; ++nt)
                    mma16816(cf[mt][nt][0], cf[mt][nt][1], cf[mt][nt][2], cf[mt][nt][3],
                             af[mt][0], af[mt][1], af[mt][2], af[mt][3],
                             bfr[nt][0], bfr[nt][1]);
        }
        // store next chunk into other buffer
        if (c < 47) {
            char* dA = smA + ((c + 1) & 1) * 16384;
            char* dB = smB + ((c + 1) & 1) * 16384;
#pragma unroll
            for (int i = 0; i < 4; ++i) {
                int r = ldr + i * 32;
                uint32_t so = r * 128 + ((ldc ^ (r & 7)) << 4);
                *(uint4*)(dA + so) = pva[i];
                *(uint4*)(dB + so) = pvb[i];
            }
        }
        __syncthreads();
    }

    // epilogue: direct global stores + bias
#pragma unroll
    for (int mt = 0; mt < 4; ++mt) {
        const int r0 = row0 + wm + mt * 16 + (lane >> 2);
#pragma unroll
        for (int nt = 0; nt < 4; ++nt) {
            const int ccol = col0 + wn + nt * 8 + ((lane & 3) << 1);
            const float2 bv = *(const float2*)&bias[ccol];
            float2 v0 = make_float2(cf[mt][nt][0] + bv.x, cf[mt][nt][1] + bv.y);
            float2 v1 = make_float2(cf[mt][nt][2] + bv.x, cf[mt][nt][3] + bv.y);
            *(float2*)&C[(size_t)r0 * 1024 + ccol]       = v0;
            *(float2*)&C[(size_t)(r0 + 8) * 1024 + ccol] = v1;
        }
    }
}

// =====================================================================
// K2: per (b,h,seg): P = (elu(K)+1)^T @ V  [128x128], Zseg = 512*colsum
// =====================================================================
__global__ __launch_bounds__(256) void k_kvouter()
{
    const int idx = blockIdx.x;                  // b*128 + h*16 + seg
    const int b = idx >> 7, h = (idx >> 4) & 7, seg = idx & 15;
    __shared__ __align__(16) float sks[16][128];
    __shared__ __align__(16) float vvs[16][128];
    const int tid = threadIdx.x, tx = tid & 15, ty = tid >> 4;
    const int lr = tid >> 5, c4 = (tid & 31) << 2;

    ull_t acc[8][4];
#pragma unroll
    for (int i = 0; i < 8; ++i)
#pragma unroll
        for (int j = 0; j < 4; ++j) acc[i][j] = 0ull;
    float zacc[8] = {0.f,0.f,0.f,0.f,0.f,0.f,0.f,0.f};

    const size_t rowbase = (size_t)(b * 8192 + seg * 512) * 1024 + h * 128;

    for (int l0 = 0; l0 < 512; l0 += 16) {
        float4 k0v = *(const float4*)(g_K + rowbase + (size_t)(l0 + lr) * 1024 + c4);
        float4 k1v = *(const float4*)(g_K + rowbase + (size_t)(l0 + lr + 8) * 1024 + c4);
        float4 v0v = *(const float4*)(g_V + rowbase + (size_t)(l0 + lr) * 1024 + c4);
        float4 v1v = *(const float4*)(g_V + rowbase + (size_t)(l0 + lr + 8) * 1024 + c4);
        k0v.x = elup1(k0v.x); k0v.y = elup1(k0v.y); k0v.z = elup1(k0v.z); k0v.w = elup1(k0v.w);
        k1v.x = elup1(k1v.x); k1v.y = elup1(k1v.y); k1v.z = elup1(k1v.z); k1v.w = elup1(k1v.w);
        __syncthreads();
        *(float4*)&sks[lr][c4]     = k0v;
        *(float4*)&sks[lr + 8][c4] = k1v;
        *(float4*)&vvs[lr][c4]     = v0v;
        *(float4*)&vvs[lr + 8][c4] = v1v;
        __syncthreads();
#pragma unroll
        for (int l = 0; l < 16; ++l) {
            float4 a0 = *(const float4*)&sks[l][ty * 8];
            float4 a1 = *(const float4*)&sks[l][ty * 8 + 4];
            ulonglong2 b01 = *(const ulonglong2*)&vvs[l][tx * 8];
            ulonglong2 b23 = *(const ulonglong2*)&vvs[l][tx * 8 + 4];
            if (tx == 0) {
                zacc[0] += a0.x; zacc[1] += a0.y; zacc[2] += a0.z; zacc[3] += a0.w;
                zacc[4] += a1.x; zacc[5] += a1.y; zacc[6] += a1.z; zacc[7] += a1.w;
            }
            FMA8x4(acc[0], a0.x, b01, b23);
            FMA8x4(acc[1], a0.y, b01, b23);
            FMA8x4(acc[2], a0.z, b01, b23);
            FMA8x4(acc[3], a0.w, b01, b23);
            FMA8x4(acc[4], a1.x, b01, b23);
            FMA8x4(acc[5], a1.y, b01, b23);
            FMA8x4(acc[6], a1.z, b01, b23);
            FMA8x4(acc[7], a1.w, b01, b23);
        }
    }
    const size_t pbase = (size_t)idx * 16384;
#pragma unroll
    for (int i = 0; i < 8; ++i) {
        size_t rb = pbase + (size_t)(ty * 8 + i) * 128 + tx * 8;
#pragma unroll
        for (int jp = 0; jp < 4; ++jp) {
            float2 v = upk2(acc[i][jp]);
            g_P[rb + jp * 2]     = v.x;
            g_P[rb + jp * 2 + 1] = v.y;
        }
    }
    if (tx == 0) {
#pragma unroll
        for (int i = 0; i < 8; ++i)
            g_Zseg[idx * 128 + ty * 8 + i] = 512.f * zacc[i];
    }
}

// =====================================================================
// K3: inclusive prefix over seg for P -> Mem and Zseg -> Z
// =====================================================================
__global__ __launch_bounds__(256) void k_prefix()
{
    const int bh = blockIdx.x;
    const int tid = threadIdx.x;
    float acc[64];
#pragma unroll
    for (int u = 0; u < 64; ++u) acc[u] = 0.f;
    float zacc = 0.f;
    for (int seg = 0; seg < 16; ++seg) {
        const size_t base = ((size_t)bh * 16 + seg) * 16384;
#pragma unroll
        for (int u = 0; u < 64; ++u) {
            acc[u] += g_P[base + u * 256 + tid];
            g_Mem[base + u * 256 + tid] = acc[u];
        }
        if (tid < 128) {
            zacc += g_Zseg[(bh * 16 + seg) * 128 + tid];
            g_Z[(bh * 16 + seg) * 128 + tid] = zacc;
        }
    }
}

// =====================================================================
// K4: per (b,seg,qt64): loop 8 heads: softmax attn + linear retrieval,
//     head-mean beta blend
// =====================================================================
__global__ __launch_bounds__(256, 1) void k_attn(const float* __restrict__ beta,
                                                 float* __restrict__ out)
{
    extern __shared__ __align__(16) float sm[];
    float* Qs = sm;                       // [128k][64r]   = 8192
    float* KV = sm + 8192;                // 8192
    float* Sc = sm + 16384;               // [64][516]     = 33024
    float* zs = sm + 49408;               // 128
    float* rs = sm + 49536;               // 64

    const int idx = blockIdx.x;           // b*128 + seg*8 + qt
    const int b = idx >> 7, seg = (idx >> 3) & 15, qt = idx & 7;
    const int tid = threadIdx.x, tx = tid & 15, ty = tid >> 4;
    const float bsig = 1.f / (1.f + __expf(-beta[0]));
    const float bsig8 = bsig * 0.125f, obsig8 = (1.f - bsig) * 0.125f;
    const float scale = 0.088388347648318447f;    // 1/sqrt(128)
    const int qrow0 = b * 8192 + seg * 512 + qt * 64;
    const int krow0 = b * 8192 + seg * 512;

    const int r4 = tid >> 2, p32 = (tid & 3) * 32;
    const float* QLsrc = g_Q + (size_t)(qrow0 + r4) * 1024 + p32;

    float facc[4][8];
#pragma unroll
    for (int i = 0; i < 4; ++i)
#pragma unroll
        for (int j = 0; j < 8; ++j) facc[i][j] = 0.f;

    for (int h = 0; h < 8; ++h) {
        const int hc = h * 128;
        __syncthreads();
#pragma unroll
        for (int u = 0; u < 8; ++u) {
            float4 v = *(const float4*)(QLsrc + hc + u * 4);
            Qs[(p32 + u * 4 + 0) * 64 + r4] = v.x;
            Qs[(p32 + u * 4 + 1) * 64 + r4] = v.y;
            Qs[(p32 + u * 4 + 2) * 64 + r4] = v.z;
            Qs[(p32 + u * 4 + 3) * 64 + r4] = v.w;
        }
        if (tid < 128)
            zs[tid] = g_Z[((size_t)(b * 8 + h) * 16 + seg) * 128 + tid];

        for (int kc = 0; kc < 8; ++kc) {
            float4 ld[8];
            const float* src = g_K + (size_t)(krow0 + kc * 64 + r4) * 1024 + hc + p32;
#pragma unroll
            for (int u = 0; u < 8; ++u) ld[u] = *(const float4*)(src + u * 4);
            __syncthreads();
#pragma unroll
            for (int u = 0; u < 8; ++u) {
                KV[(p32 + u * 4 + 0) * 64 + r4] = ld[u].x;
                KV[(p32 + u * 4 + 1) * 64 + r4] = ld[u].y;
                KV[(p32 + u * 4 + 2) * 64 + r4] = ld[u].z;
                KV[(p32 + u * 4 + 3) * 64 + r4] = ld[u].w;
            }
            __syncthreads();
            ull_t sacc[4][2];
#pragma unroll
            for (int i = 0; i < 4; ++i) { sacc[i][0] = 0ull; sacc[i][1] = 0ull; }
#pragma unroll 8
            for (int kk = 0; kk < 128; ++kk) {
                float4 a = *(const float4*)&Qs[kk * 64 + ty * 4];
                ulonglong2 bb = *(const ulonglong2*)&KV[kk * 64 + tx * 4];
                ull_t ad;
                ad = pk2(a.x, a.x); fma2(sacc[0][0], ad, bb.x); fma2(sacc[0][1], ad, bb.y);
                ad = pk2(a.y, a.y); fma2(sacc[1][0], ad, bb.x); fma2(sacc[1][1], ad, bb.y);
                ad = pk2(a.z, a.z); fma2(sacc[2][0], ad, bb.x); fma2(sacc[2][1], ad, bb.y);
                ad = pk2(a.w, a.w); fma2(sacc[3][0], ad, bb.x); fma2(sacc[3][1], ad, bb.y);
            }
#pragma unroll
            for (int i = 0; i < 4; ++i) {
                float* dst = &Sc[(ty * 4 + i) * 516 + kc * 64 + tx * 4];
                float2 v0 = upk2(sacc[i][0]), v1 = upk2(sacc[i][1]);
                dst[0] = v0.x * scale; dst[1] = v0.y * scale;
                dst[2] = v1.x * scale; dst[3] = v1.y * scale;
            }
        }
        __syncthreads();
        for (int u = tid; u < 8192; u += 256) Qs[u] = elup1(Qs[u]);
        {
            const int row = tid >> 2, part = tid & 3;
            float* rowp = &Sc[row * 516 + part * 128];
            float m = -1e30f;
#pragma unroll 8
            for (int j = 0; j < 128; ++j) m = fmaxf(m, rowp[j]);
            m = fmaxf(m, __shfl_xor_sync(0xffffffffu, m, 1));
            m = fmaxf(m, __shfl_xor_sync(0xffffffffu, m, 2));
            float s = 0.f;
#pragma unroll 8
            for (int j = 0; j < 128; ++j) { float e = __expf(rowp[j] - m); rowp[j] = e; s += e; }
            s += __shfl_xor_sync(0xffffffffu, s, 1);
            s += __shfl_xor_sync(0xffffffffu, s, 2);
            if (part == 0) rs[row] = s;
        }
        __syncthreads();

        ull_t dacc[4][4];
#pragma unroll
        for (int i = 0; i < 4; ++i)
#pragma unroll
            for (int j = 0; j < 4; ++j) dacc[i][j] = 0ull;
        for (int kc = 0; kc < 8; ++kc) {
            float4 ld[8];
            const float* src = g_V + (size_t)(krow0 + kc * 64 + r4) * 1024 + hc + p32;
#pragma unroll
            for (int u = 0; u < 8; ++u) ld[u] = *(const float4*)(src + u * 4);
            __syncthreads();
#pragma unroll
            for (int u = 0; u < 8; ++u)
                *(float4*)&KV[r4 * 128 + p32 + u * 4] = ld[u];
            __syncthreads();
#pragma unroll 4
            for (int kk = 0; kk < 64; ++kk) {
                ulonglong2 b01 = *(const ulonglong2*)&KV[kk * 128 + tx * 8];
                ulonglong2 b23 = *(const ulonglong2*)&KV[kk * 128 + tx * 8 + 4];
                const float* ap = &Sc[(ty * 4) * 516 + kc * 64 + kk];
                FMA8x4(dacc[0], ap[0],     b01, b23);
                FMA8x4(dacc[1], ap[516],   b01, b23);
                FMA8x4(dacc[2], ap[1032],  b01, b23);
                FMA8x4(dacc[3], ap[1548],  b01, b23);
            }
        }

        ull_t macc[4][4];
#pragma unroll
        for (int i = 0; i < 4; ++i)
#pragma unroll
            for (int j = 0; j < 4; ++j) macc[i][j] = 0ull;
        float den[4] = {0.f, 0.f, 0.f, 0.f};
        const size_t membase = ((size_t)(b * 8 + h) * 16 + seg) * 16384;
        for (int mc = 0; mc < 2; ++mc) {
            float4 ld[8];
            const float* src = g_Mem + membase + (size_t)(mc * 64 + r4) * 128 + p32;
#pragma unroll
            for (int u = 0; u < 8; ++u) ld[u] = *(const float4*)(src + u * 4);
            __syncthreads();
#pragma unroll
            for (int u = 0; u < 8; ++u)
                *(float4*)&KV[r4 * 128 + p32 + u * 4] = ld[u];
            __syncthreads();
#pragma unroll 4
            for (int kk = 0; kk < 64; ++kk) {
                const int kg = mc * 64 + kk;
                ulonglong2 b01 = *(const ulonglong2*)&KV[kk * 128 + tx * 8];
                ulonglong2 b23 = *(const ulonglong2*)&KV[kk * 128 + tx * 8 + 4];
                const float zk = zs[kg];
                const float* ap = &Qs[kg * 64 + ty * 4];
                den[0] += ap[0] * zk; FMA8x4(macc[0], ap[0], b01, b23);
                den[1] += ap[1] * zk; FMA8x4(macc[1], ap[1], b01, b23);
                den[2] += ap[2] * zk; FMA8x4(macc[2], ap[2], b01, b23);
                den[3] += ap[3] * zk; FMA8x4(macc[3], ap[3], b01, b23);
            }
        }

#pragma unroll
        for (int i = 0; i < 4; ++i) {
            const float minv = bsig8 / (den[i] + 1e-5f);
            const float dinv = obsig8 / rs[ty * 4 + i];
#pragma unroll
            for (int jp = 0; jp < 4; ++jp) {
                float2 dv = upk2(dacc[i][jp]);
                float2 mv = upk2(macc[i][jp]);
                facc[i][jp * 2]     += mv.x * minv + dv.x * dinv;
                facc[i][jp * 2 + 1] += mv.y * minv + dv.y * dinv;
            }
        }
    }

#pragma unroll
    for (int i = 0; i < 4; ++i) {
        float* dst = out + (size_t)(qrow0 + ty * 4 + i) * 128 + tx * 8;
#pragma unroll
        for (int j = 0; j < 8; ++j) dst[j] = facc[i][j];
    }
}

// =====================================================================
extern "C" void kernel_launch(void* const* d_in, const int* in_sizes, int n_in,
                              void* d_out, int out_size)
{
    const float* x    = (const float*)d_in[0];
    const float* wq   = (const float*)d_in[1];
    const float* bq   = (const float*)d_in[2];
    const float* wk   = (const float*)d_in[3];
    const float* bk   = (const float*)d_in[4];
    const float* wv   = (const float*)d_in[5];
    const float* bv   = (const float*)d_in[6];
    const float* beta = (const float*)d_in[7];
    float* out = (float*)d_out;

    static int attr_set = 0;
    if (!attr_set) {
        cudaFuncSetAttribute(k_attn, cudaFuncAttributeMaxDynamicSharedMemorySize, 198400);
        cudaFuncSetAttribute(k_proj_mma, cudaFuncAttributeMaxDynamicSharedMemorySize, 65536);
        attr_set = 1;
    }

    k_splitX<<<32768, 256>>>(x);
    k_splitW<<<dim3(32, 32), 256>>>(wq, 0);
    k_splitW<<<dim3(32, 32), 256>>>(wk, 1);
    k_splitW<<<dim3(32, 32), 256>>>(wv, 2);
    dim3 gp(8, 256);
    k_proj_mma<<<gp, 256, 65536>>>(bq, 0);
    k_proj_mma<<<gp, 256, 65536>>>(bk, 1);
    k_proj_mma<<<gp, 256, 65536>>>(bv, 2);
    k_kvouter<<<512, 256>>>();
    k_prefix<<<32, 256>>>();
    k_attn<<<512, 256, 198400>>>(beta, out);
}

// round 6
// speedup vs baseline: 2.1667x; 1.5531x over previous
#include <cuda_runtime.h>
#include <cuda_bf16.h>
#include <cstdint>

typedef unsigned long long ull_t;

// ---------- packed fp32x2 helpers ----------
__device__ __forceinline__ ull_t pk2(float x, float y){
    ull_t r; asm("mov.b64 %0, {%1,%2};" : "=l"(r) : "f"(x), "f"(y)); return r;
}
__device__ __forceinline__ void fma2(ull_t &d, ull_t a, ull_t b){
    asm("fma.rn.f32x2 %0, %1, %2, %0;" : "+l"(d) : "l"(a), "l"(b));
}
__device__ __forceinline__ float2 upk2(ull_t v){
    float lo, hi; asm("mov.b64 {%0,%1}, %2;" : "=f"(lo), "=f"(hi) : "l"(v));
    return make_float2(lo, hi);
}
__device__ __forceinline__ float elup1(float x){ return x > 0.f ? x + 1.f : __expf(x); }

#define FMA8x4(ACCROW, AV, B01, B23) do { ull_t ad_ = pk2((AV),(AV)); \
    fma2((ACCROW)[0], ad_, (B01).x); fma2((ACCROW)[1], ad_, (B01).y); \
    fma2((ACCROW)[2], ad_, (B23).x); fma2((ACCROW)[3], ad_, (B23).y); } while(0)

// ---------- warp MMA helpers ----------
__device__ __forceinline__ uint32_t smem_u32(const void* p){
    uint32_t a;
    asm("{ .reg .u64 t; cvta.to.shared.u64 t, %1; cvt.u32.u64 %0, t; }" : "=r"(a) : "l"(p));
    return a;
}
__device__ __forceinline__ void ldsm_x4(uint32_t &r0, uint32_t &r1, uint32_t &r2, uint32_t &r3, uint32_t addr){
    asm volatile("ldmatrix.sync.aligned.m8n8.x4.shared.b16 {%0,%1,%2,%3}, [%4];"
        : "=r"(r0), "=r"(r1), "=r"(r2), "=r"(r3) : "r"(addr));
}
__device__ __forceinline__ void ldsm_x2(uint32_t &r0, uint32_t &r1, uint32_t addr){
    asm volatile("ldmatrix.sync.aligned.m8n8.x2.shared.b16 {%0,%1}, [%2];"
        : "=r"(r0), "=r"(r1) : "r"(addr));
}
__device__ __forceinline__ void ldsm_x2t(uint32_t &r0, uint32_t &r1, uint32_t addr){
    asm volatile("ldmatrix.sync.aligned.m8n8.x2.trans.shared.b16 {%0,%1}, [%2];"
        : "=r"(r0), "=r"(r1) : "r"(addr));
}
__device__ __forceinline__ void mma16816(float &c0, float &c1, float &c2, float &c3,
                                         uint32_t a0, uint32_t a1, uint32_t a2, uint32_t a3,
                                         uint32_t b0, uint32_t b1){
    asm volatile("mma.sync.aligned.m16n8k16.row.col.f32.bf16.bf16.f32 "
        "{%0,%1,%2,%3}, {%4,%5,%6,%7}, {%8,%9}, {%0,%1,%2,%3};"
        : "+f"(c0), "+f"(c1), "+f"(c2), "+f"(c3)
        : "r"(a0), "r"(a1), "r"(a2), "r"(a3), "r"(b0), "r"(b1));
}
__device__ __forceinline__ uint32_t swu(int u, int r){ return (uint32_t)((u & 8) | ((u & 7) ^ (r & 7))); }
__device__ __forceinline__ uint32_t packh(float a, float b){
    __nv_bfloat162 t = __halves2bfloat162(__float2bfloat16_rn(a), __float2bfloat16_rn(b));
    return *(uint32_t*)&t;
}
__device__ __forceinline__ void bsplit2(__nv_bfloat16* H, __nv_bfloat16* L, size_t off, float2 v){
    __nv_bfloat16 hx = __float2bfloat16_rn(v.x), hy = __float2bfloat16_rn(v.y);
    __nv_bfloat16 lx = __float2bfloat16_rn(v.x - __bfloat162float(hx));
    __nv_bfloat16 ly = __float2bfloat16_rn(v.y - __bfloat162float(hy));
    *(__nv_bfloat162*)(H + off) = __halves2bfloat162(hx, hy);
    *(__nv_bfloat162*)(L + off) = __halves2bfloat162(lx, ly);
}

// ---------- dims: B=4, S=8192, D=1024, H=8, dk=dv=128, SEG=512, nseg=16 ----------

// ---------- device scratch ----------
__device__ float g_K[33554432];
__device__ float g_V[33554432];
__device__ float g_P[8388608];
__device__ float g_Mem[8388608];
__device__ float g_Zseg[65536];
__device__ float g_Z[65536];
__device__ __nv_bfloat16 g_Xh[33554432];
__device__ __nv_bfloat16 g_Xl[33554432];
__device__ __nv_bfloat16 g_Wth[3145728];
__device__ __nv_bfloat16 g_Wtl[3145728];
__device__ __nv_bfloat16 g_Qh[33554432];
__device__ __nv_bfloat16 g_Ql[33554432];
__device__ __nv_bfloat16 g_Kh[33554432];
__device__ __nv_bfloat16 g_Kl[33554432];
__device__ __nv_bfloat16 g_Vh[33554432];
__device__ __nv_bfloat16 g_Vl[33554432];
__device__ __nv_bfloat16 g_Memh[8388608];
__device__ __nv_bfloat16 g_Meml[8388608];

// =====================================================================
// S1: split X into bf16 hi/lo
// =====================================================================
__global__ __launch_bounds__(256) void k_splitX(const float* __restrict__ x)
{
    size_t i = ((size_t)blockIdx.x * 256 + threadIdx.x) * 4;
    float4 v = *(const float4*)(x + i);
    bsplit2(g_Xh, g_Xl, i,     make_float2(v.x, v.y));
    bsplit2(g_Xh, g_Xl, i + 2, make_float2(v.z, v.w));
}

// =====================================================================
// S2: transpose + split W[k][n] -> Wt[n][k] bf16 hi/lo
// =====================================================================
__global__ __launch_bounds__(256) void k_splitW(const float* __restrict__ w, int which)
{
    __shared__ float t[32][33];
    const int bx = blockIdx.x << 5, by = blockIdx.y << 5;
    const int tx = threadIdx.x & 31, ty = threadIdx.x >> 5;
#pragma unroll
    for (int r = 0; r < 4; ++r)
        t[ty * 4 + r][tx] = w[(size_t)(by + ty * 4 + r) * 1024 + bx + tx];
    __syncthreads();
    __nv_bfloat16* Ht = g_Wth + (size_t)which * 1048576;
    __nv_bfloat16* Lt = g_Wtl + (size_t)which * 1048576;
#pragma unroll
    for (int r = 0; r < 4; ++r) {
        int n = bx + ty * 4 + r, k = by + tx;
        float val = t[tx][ty * 4 + r];
        __nv_bfloat16 h = __float2bfloat16_rn(val);
        __nv_bfloat16 l = __float2bfloat16_rn(val - __bfloat162float(h));
        Ht[(size_t)n * 1024 + k] = h;
        Lt[(size_t)n * 1024 + k] = l;
    }
}

// =====================================================================
// K1: bf16 mma.sync projection GEMM, split-bf16 3-pass (K_eff = 3072)
//     Epilogue writes fp32 (K,V only) + bf16 hi/lo splits (all)
// =====================================================================
__global__ __launch_bounds__(256, 1) void k_proj_mma(const float* __restrict__ bias, int which)
{
    extern __shared__ __align__(128) char sm_raw[];
    char* smA = sm_raw;
    char* smB = sm_raw + 32768;
    const uint32_t baseA = smem_u32(smA);
    const uint32_t baseB = smem_u32(smB);

    float* __restrict__ C = (which == 1) ? g_K : g_V;
    __nv_bfloat16* Hd = (which == 0) ? g_Qh : ((which == 1) ? g_Kh : g_Vh);
    __nv_bfloat16* Ld = (which == 0) ? g_Ql : ((which == 1) ? g_Kl : g_Vl);
    const __nv_bfloat16* Wh = g_Wth + (size_t)which * 1048576;
    const __nv_bfloat16* Wl = g_Wtl + (size_t)which * 1048576;

    const int tid = threadIdx.x, lane = tid & 31, wid = tid >> 5;
    const int wm = (wid >> 2) * 64, wn = (wid & 3) * 32;
    const int row0 = blockIdx.y << 7, col0 = blockIdx.x << 7;
    const int ldr = tid >> 3, ldc = tid & 7;

    const int rowA = wm + (lane & 15);
    const int rA7 = rowA & 7;
    const int unA = lane >> 4;
    const int rowB = wn + (lane & 7);
    const int rB7 = lane & 7;
    const int unB = (lane >> 3) & 1;

    float cf[4][4][4];
#pragma unroll
    for (int mt = 0; mt < 4; ++mt)
#pragma unroll
        for (int nt = 0; nt < 4; ++nt)
#pragma unroll
            for (int q = 0; q < 4; ++q) cf[mt][nt][q] = 0.f;

    uint4 pva[4], pvb[4];
    {
#pragma unroll
        for (int i = 0; i < 4; ++i) {
            int r = ldr + i * 32;
            pva[i] = *(const uint4*)(g_Xh + (size_t)(row0 + r) * 1024 + ldc * 8);
            pvb[i] = *(const uint4*)(Wh + (size_t)(col0 + r) * 1024 + ldc * 8);
        }
#pragma unroll
        for (int i = 0; i < 4; ++i) {
            int r = ldr + i * 32;
            uint32_t so = r * 128 + ((ldc ^ (r & 7)) << 4);
            *(uint4*)(smA + so) = pva[i];
            *(uint4*)(smB + so) = pvb[i];
        }
    }
    __syncthreads();

    for (int c = 0; c < 48; ++c) {
        const int buf = c & 1;
        if (c < 47) {
            const int cn = c + 1;
            const int p = cn >> 4, k0 = (cn & 15) << 6;
            const __nv_bfloat16* As = (p < 2) ? g_Xh : g_Xl;
            const __nv_bfloat16* Bs = (p == 1) ? Wl : Wh;
#pragma unroll
            for (int i = 0; i < 4; ++i) {
                int r = ldr + i * 32;
                pva[i] = *(const uint4*)(As + (size_t)(row0 + r) * 1024 + k0 + ldc * 8);
                pvb[i] = *(const uint4*)(Bs + (size_t)(col0 + r) * 1024 + k0 + ldc * 8);
            }
        }
        const uint32_t bA = baseA + buf * 16384;
        const uint32_t bB = baseB + buf * 16384;
#pragma unroll
        for (int ks = 0; ks < 4; ++ks) {
            uint32_t af[4][4];
            uint32_t bfr[4][2];
#pragma unroll
            for (int mt = 0; mt < 4; ++mt) {
                uint32_t addr = bA + (rowA + mt * 16) * 128 + ((((ks << 1) + unA) ^ rA7) << 4);
                ldsm_x4(af[mt][0], af[mt][1], af[mt][2], af[mt][3], addr);
            }
#pragma unroll
            for (int nt = 0; nt < 4; ++nt) {
                uint32_t addr = bB + (rowB + nt * 8) * 128 + ((((ks << 1) + unB) ^ rB7) << 4);
                ldsm_x2(bfr[nt][0], bfr[nt][1], addr);
            }
#pragma unroll
            for (int mt = 0; mt < 4; ++mt)
#pragma unroll
                for (int nt = 0; nt < 4; ++nt)
                    mma16816(cf[mt][nt][0], cf[mt][nt][1], cf[mt][nt][2], cf[mt][nt][3],
                             af[mt][0], af[mt][1], af[mt][2], af[mt][3],
                             bfr[nt][0], bfr[nt][1]);
        }
        if (c < 47) {
            char* dA = smA + ((c + 1) & 1) * 16384;
            char* dB = smB + ((c + 1) & 1) * 16384;
#pragma unroll
            for (int i = 0; i < 4; ++i) {
                int r = ldr + i * 32;
                uint32_t so = r * 128 + ((ldc ^ (r & 7)) << 4);
                *(uint4*)(dA + so) = pva[i];
                *(uint4*)(dB + so) = pvb[i];
            }
        }
        __syncthreads();
    }

#pragma unroll
    for (int mt = 0; mt < 4; ++mt) {
        const int r0 = row0 + wm + mt * 16 + (lane >> 2);
#pragma unroll
        for (int nt = 0; nt < 4; ++nt) {
            const int ccol = col0 + wn + nt * 8 + ((lane & 3) << 1);
            const float2 bv = *(const float2*)&bias[ccol];
            float2 v0 = make_float2(cf[mt][nt][0] + bv.x, cf[mt][nt][1] + bv.y);
            float2 v1 = make_float2(cf[mt][nt][2] + bv.x, cf[mt][nt][3] + bv.y);
            size_t o0 = (size_t)r0 * 1024 + ccol;
            size_t o1 = o0 + 8 * 1024;
            if (which) {
                *(float2*)&C[o0] = v0;
                *(float2*)&C[o1] = v1;
            }
            bsplit2(Hd, Ld, o0, v0);
            bsplit2(Hd, Ld, o1, v1);
        }
    }
}

// =====================================================================
// K2: per (b,h,seg): P = (elu(K)+1)^T @ V  [128x128], Zseg = 512*colsum
// =====================================================================
__global__ __launch_bounds__(256) void k_kvouter()
{
    const int idx = blockIdx.x;
    const int b = idx >> 7, h = (idx >> 4) & 7, seg = idx & 15;
    __shared__ __align__(16) float sks[16][128];
    __shared__ __align__(16) float vvs[16][128];
    const int tid = threadIdx.x, tx = tid & 15, ty = tid >> 4;
    const int lr = tid >> 5, c4 = (tid & 31) << 2;

    ull_t acc[8][4];
#pragma unroll
    for (int i = 0; i < 8; ++i)
#pragma unroll
        for (int j = 0; j < 4; ++j) acc[i][j] = 0ull;
    float zacc[8] = {0.f,0.f,0.f,0.f,0.f,0.f,0.f,0.f};

    const size_t rowbase = (size_t)(b * 8192 + seg * 512) * 1024 + h * 128;

    for (int l0 = 0; l0 < 512; l0 += 16) {
        float4 k0v = *(const float4*)(g_K + rowbase + (size_t)(l0 + lr) * 1024 + c4);
        float4 k1v = *(const float4*)(g_K + rowbase + (size_t)(l0 + lr + 8) * 1024 + c4);
        float4 v0v = *(const float4*)(g_V + rowbase + (size_t)(l0 + lr) * 1024 + c4);
        float4 v1v = *(const float4*)(g_V + rowbase + (size_t)(l0 + lr + 8) * 1024 + c4);
        k0v.x = elup1(k0v.x); k0v.y = elup1(k0v.y); k0v.z = elup1(k0v.z); k0v.w = elup1(k0v.w);
        k1v.x = elup1(k1v.x); k1v.y = elup1(k1v.y); k1v.z = elup1(k1v.z); k1v.w = elup1(k1v.w);
        __syncthreads();
        *(float4*)&sks[lr][c4]     = k0v;
        *(float4*)&sks[lr + 8][c4] = k1v;
        *(float4*)&vvs[lr][c4]     = v0v;
        *(float4*)&vvs[lr + 8][c4] = v1v;
        __syncthreads();
#pragma unroll
        for (int l = 0; l < 16; ++l) {
            float4 a0 = *(const float4*)&sks[l][ty * 8];
            float4 a1 = *(const float4*)&sks[l][ty * 8 + 4];
            ulonglong2 b01 = *(const ulonglong2*)&vvs[l][tx * 8];
            ulonglong2 b23 = *(const ulonglong2*)&vvs[l][tx * 8 + 4];
            if (tx == 0) {
                zacc[0] += a0.x; zacc[1] += a0.y; zacc[2] += a0.z; zacc[3] += a0.w;
                zacc[4] += a1.x; zacc[5] += a1.y; zacc[6] += a1.z; zacc[7] += a1.w;
            }
            FMA8x4(acc[0], a0.x, b01, b23);
            FMA8x4(acc[1], a0.y, b01, b23);
            FMA8x4(acc[2], a0.z, b01, b23);
            FMA8x4(acc[3], a0.w, b01, b23);
            FMA8x4(acc[4], a1.x, b01, b23);
            FMA8x4(acc[5], a1.y, b01, b23);
            FMA8x4(acc[6], a1.z, b01, b23);
            FMA8x4(acc[7], a1.w, b01, b23);
        }
    }
    const size_t pbase = (size_t)idx * 16384;
#pragma unroll
    for (int i = 0; i < 8; ++i) {
        size_t rb = pbase + (size_t)(ty * 8 + i) * 128 + tx * 8;
#pragma unroll
        for (int jp = 0; jp < 4; ++jp) {
            float2 v = upk2(acc[i][jp]);
            g_P[rb + jp * 2]     = v.x;
            g_P[rb + jp * 2 + 1] = v.y;
        }
    }
    if (tx == 0) {
#pragma unroll
        for (int i = 0; i < 8; ++i)
            g_Zseg[idx * 128 + ty * 8 + i] = 512.f * zacc[i];
    }
}

// =====================================================================
// K3: inclusive prefix over seg; writes fp32 Mem + bf16 hi/lo splits + Z
// =====================================================================
__global__ __launch_bounds__(256) void k_prefix()
{
    const int bh = blockIdx.x;
    const int tid = threadIdx.x;
    float acc[64];
#pragma unroll
    for (int u = 0; u < 64; ++u) acc[u] = 0.f;
    float zacc = 0.f;
    for (int seg = 0; seg < 16; ++seg) {
        const size_t base = ((size_t)bh * 16 + seg) * 16384;
#pragma unroll
        for (int u = 0; u < 64; ++u) {
            acc[u] += g_P[base + u * 256 + tid];
            g_Mem[base + u * 256 + tid] = acc[u];
            float v = acc[u];
            __nv_bfloat16 h = __float2bfloat16_rn(v);
            __nv_bfloat16 l = __float2bfloat16_rn(v - __bfloat162float(h));
            g_Memh[base + u * 256 + tid] = h;
            g_Meml[base + u * 256 + tid] = l;
        }
        if (tid < 128) {
            zacc += g_Zseg[(bh * 16 + seg) * 128 + tid];
            g_Z[(bh * 16 + seg) * 128 + tid] = zacc;
        }
    }
}

// =====================================================================
// K4: mma.sync attention. CTA=(b,seg,qt64), 8 warps, loops 8 heads.
// smem: Sc fp32 [64][516] | sAh/sAl [64][128]bf16 | sBh/sBl [128][128]bf16
// =====================================================================
__global__ __launch_bounds__(256, 1) void k_attn_mma(const float* __restrict__ beta,
                                                     float* __restrict__ out)
{
    extern __shared__ __align__(16) char smraw[];
    float* Sc = (float*)smraw;                       // 132096 B
    char* sAh = smraw + 132096;                      // 16384
    char* sAl = sAh + 16384;                         // 16384
    char* sBh = sAl + 16384;                         // 32768
    char* sBl = sBh + 32768;                         // 32768
    float* zs  = (float*)(sBl + 32768);              // 128
    float* rs  = zs + 128;                           // 64
    float* den = rs + 64;                            // 64
    const uint32_t aAh = smem_u32(sAh), aAl = smem_u32(sAl);
    const uint32_t aBh = smem_u32(sBh), aBl = smem_u32(sBl);

    const int idx = blockIdx.x;                      // b*128 + seg*8 + qt
    const int b = idx >> 7, seg = (idx >> 3) & 15, qt = idx & 7;
    const int tid = threadIdx.x, lane = tid & 31, wid = tid >> 5;
    const int wm2 = (wid >> 2) * 32, wn2 = (wid & 3) * 32;
    const int qrow0 = b * 8192 + seg * 512 + qt * 64;
    const int krow0 = b * 8192 + seg * 512;
    const float bsig = 1.f / (1.f + __expf(-beta[0]));
    const float bsig8 = bsig * 0.125f, obsig8 = (1.f - bsig) * 0.125f;
    const float scale = 0.088388347648318447f;

    // ldmatrix per-thread bases
    const int rowA0 = wm2 + (lane & 15);             // + mt*16
    const int unA = lane >> 4;
    const int rowBn = wn2 + (lane & 7);              // + nt*8 (non-trans B)
    const int unB = (lane >> 3) & 1;
    const int rowKt = (lane & 7) + ((lane >> 3) & 1) * 8;  // + ks*16 (trans B)
    // softmax / transform mapping
    const int srow = tid >> 2, spart = tid & 3;

    float facc[2][4][4];
#pragma unroll
    for (int mt = 0; mt < 2; ++mt)
#pragma unroll
        for (int nt = 0; nt < 4; ++nt)
#pragma unroll
            for (int q = 0; q < 4; ++q) facc[mt][nt][q] = 0.f;

    for (int h = 0; h < 8; ++h) {
        const int hc = h * 128;
        __syncthreads();   // sA free (prev head PV done)
        // ---- load Q tile splits into sA ----
#pragma unroll
        for (int it = 0; it < 4; ++it) {
            int i2 = it * 256 + tid;
            int r = i2 >> 4, u = i2 & 15;
            size_t gs = (size_t)(qrow0 + r) * 1024 + hc + u * 8;
            uint32_t so = r * 256 + (swu(u, r) << 4);
            *(uint4*)(sAh + so) = *(const uint4*)(g_Qh + gs);
            *(uint4*)(sAl + so) = *(const uint4*)(g_Ql + gs);
        }
        if (tid < 128)
            zs[tid] = g_Z[((size_t)(b * 8 + h) * 16 + seg) * 128 + tid];

        // ---- scores: 4 key chunks of 128 ----
        for (int kc = 0; kc < 4; ++kc) {
            __syncthreads();   // prev chunk mma done; Q stores visible (kc==0)
#pragma unroll
            for (int it = 0; it < 8; ++it) {
                int i2 = it * 256 + tid;
                int r = i2 >> 4, u = i2 & 15;
                size_t gs = (size_t)(krow0 + kc * 128 + r) * 1024 + hc + u * 8;
                uint32_t so = r * 256 + (swu(u, r) << 4);
                *(uint4*)(sBh + so) = *(const uint4*)(g_Kh + gs);
                *(uint4*)(sBl + so) = *(const uint4*)(g_Kl + gs);
            }
            __syncthreads();
            float acc[2][4][4];
#pragma unroll
            for (int mt = 0; mt < 2; ++mt)
#pragma unroll
                for (int nt = 0; nt < 4; ++nt)
#pragma unroll
                    for (int q = 0; q < 4; ++q) acc[mt][nt][q] = 0.f;
            for (int pass = 0; pass < 3; ++pass) {
                const uint32_t Ab = (pass < 2) ? aAh : aAl;
                const uint32_t Bb = (pass == 1) ? aBl : aBh;
#pragma unroll
                for (int ks = 0; ks < 8; ++ks) {
                    uint32_t af[2][4], bfr[4][2];
#pragma unroll
                    for (int mt = 0; mt < 2; ++mt)
                        ldsm_x4(af[mt][0], af[mt][1], af[mt][2], af[mt][3],
                                Ab + (rowA0 + mt * 16) * 256 + (swu(ks * 2 + unA, rowA0) << 4));
#pragma unroll
                    for (int nt = 0; nt < 4; ++nt)
                        ldsm_x2(bfr[nt][0], bfr[nt][1],
                                Bb + (rowBn + nt * 8) * 256 + (swu(ks * 2 + unB, rowBn) << 4));
#pragma unroll
                    for (int mt = 0; mt < 2; ++mt)
#pragma unroll
                        for (int nt = 0; nt < 4; ++nt)
                            mma16816(acc[mt][nt][0], acc[mt][nt][1], acc[mt][nt][2], acc[mt][nt][3],
                                     af[mt][0], af[mt][1], af[mt][2], af[mt][3],
                                     bfr[nt][0], bfr[nt][1]);
                }
            }
#pragma unroll
            for (int mt = 0; mt < 2; ++mt) {
                int r0 = wm2 + mt * 16 + (lane >> 2);
#pragma unroll
                for (int nt = 0; nt < 4; ++nt) {
                    int cc = kc * 128 + wn2 + nt * 8 + ((lane & 3) << 1);
                    *(float2*)&Sc[r0 * 516 + cc]       = make_float2(acc[mt][nt][0] * scale, acc[mt][nt][1] * scale);
                    *(float2*)&Sc[(r0 + 8) * 516 + cc] = make_float2(acc[mt][nt][2] * scale, acc[mt][nt][3] * scale);
                }
            }
        }
        __syncthreads();
        // ---- softmax (exp, row sums) ----
        {
            float* rowp = &Sc[srow * 516 + spart * 128];
            float m = -1e30f;
#pragma unroll 8
            for (int j = 0; j < 128; ++j) m = fmaxf(m, rowp[j]);
            m = fmaxf(m, __shfl_xor_sync(0xffffffffu, m, 1));
            m = fmaxf(m, __shfl_xor_sync(0xffffffffu, m, 2));
            float s = 0.f;
#pragma unroll 8
            for (int j = 0; j < 128; ++j) { float e = __expf(rowp[j] - m); rowp[j] = e; s += e; }
            s += __shfl_xor_sync(0xffffffffu, s, 1);
            s += __shfl_xor_sync(0xffffffffu, s, 2);
            if (spart == 0) rs[srow] = s;
        }
        // ---- sq = elu(Q)+1 transform in sA + exact den ----
        {
            float da = 0.f;
#pragma unroll 4
            for (int j = 0; j < 32; ++j) {
                int c = spart * 32 + j;
                uint32_t bo = srow * 256 + (swu(c >> 3, srow) << 4) + ((c & 7) << 1);
                float qh = __bfloat162float(*(__nv_bfloat16*)(sAh + bo));
                float ql = __bfloat162float(*(__nv_bfloat16*)(sAl + bo));
                float sq = elup1(qh + ql);
                da += sq * zs[c];
                __nv_bfloat16 hh = __float2bfloat16_rn(sq);
                __nv_bfloat16 ll = __float2bfloat16_rn(sq - __bfloat162float(hh));
                *(__nv_bfloat16*)(sAh + bo) = hh;
                *(__nv_bfloat16*)(sAl + bo) = ll;
            }
            da += __shfl_xor_sync(0xffffffffu, da, 1);
            da += __shfl_xor_sync(0xffffffffu, da, 2);
            if (spart == 0) den[srow] = da;
        }
        __syncthreads();
        // ---- retrieval: load Mem into sB, trans-B mma, blend minv ----
#pragma unroll
        for (int it = 0; it < 8; ++it) {
            int i2 = it * 256 + tid;
            int r = i2 >> 4, u = i2 & 15;
            size_t ms = ((size_t)(b * 8 + h) * 16 + seg) * 16384 + r * 128 + u * 8;
            uint32_t so = r * 256 + (swu(u, r) << 4);
            *(uint4*)(sBh + so) = *(const uint4*)(g_Memh + ms);
            *(uint4*)(sBl + so) = *(const uint4*)(g_Meml + ms);
        }
        __syncthreads();
        {
            float acc[2][4][4];
#pragma unroll
            for (int mt = 0; mt < 2; ++mt)
#pragma unroll
                for (int nt = 0; nt < 4; ++nt)
#pragma unroll
                    for (int q = 0; q < 4; ++q) acc[mt][nt][q] = 0.f;
            for (int pass = 0; pass < 3; ++pass) {
                const uint32_t Ab = (pass < 2) ? aAh : aAl;
                const uint32_t Bb = (pass == 1) ? aBl : aBh;
#pragma unroll
                for (int ks = 0; ks < 8; ++ks) {
                    uint32_t af[2][4], bfr[4][2];
#pragma unroll
                    for (int mt = 0; mt < 2; ++mt)
                        ldsm_x4(af[mt][0], af[mt][1], af[mt][2], af[mt][3],
                                Ab + (rowA0 + mt * 16) * 256 + (swu(ks * 2 + unA, rowA0) << 4));
                    int rK = ks * 16 + rowKt;
#pragma unroll
                    for (int nt = 0; nt < 4; ++nt)
                        ldsm_x2t(bfr[nt][0], bfr[nt][1],
                                 Bb + rK * 256 + (swu((wn2 >> 3) + nt, rK) << 4));
#pragma unroll
                    for (int mt = 0; mt < 2; ++mt)
#pragma unroll
                        for (int nt = 0; nt < 4; ++nt)
                            mma16816(acc[mt][nt][0], acc[mt][nt][1], acc[mt][nt][2], acc[mt][nt][3],
                                     af[mt][0], af[mt][1], af[mt][2], af[mt][3],
                                     bfr[nt][0], bfr[nt][1]);
                }
            }
#pragma unroll
            for (int mt = 0; mt < 2; ++mt) {
                int r0 = wm2 + mt * 16 + (lane >> 2);
                float m0 = bsig8 / (den[r0] + 1e-5f);
                float m1 = bsig8 / (den[r0 + 8] + 1e-5f);
#pragma unroll
                for (int nt = 0; nt < 4; ++nt) {
                    facc[mt][nt][0] += acc[mt][nt][0] * m0;
                    facc[mt][nt][1] += acc[mt][nt][1] * m0;
                    facc[mt][nt][2] += acc[mt][nt][2] * m1;
                    facc[mt][nt][3] += acc[mt][nt][3] * m1;
                }
            }
        }
        // ---- PV: 4 key chunks, split P into sA, V into sB, trans-B mma ----
        float dacc[2][4][4];
#pragma unroll
        for (int mt = 0; mt < 2; ++mt)
#pragma unroll
            for (int nt = 0; nt < 4; ++nt)
#pragma unroll
                for (int q = 0; q < 4; ++q) dacc[mt][nt][q] = 0.f;
        for (int kc = 0; kc < 4; ++kc) {
            __syncthreads();   // sA/sB free
#pragma unroll
            for (int it = 0; it < 4; ++it) {
                int i2 = it * 256 + tid;
                int r = i2 >> 4, u = i2 & 15;
                const float* sp = &Sc[r * 516 + kc * 128 + u * 8];
                float4 p0 = *(const float4*)sp, p1 = *(const float4*)(sp + 4);
                uint4 hi, lo;
                hi.x = packh(p0.x, p0.y); hi.y = packh(p0.z, p0.w);
                hi.z = packh(p1.x, p1.y); hi.w = packh(p1.z, p1.w);
                float2 t;
                t = upk2(pk2(p0.x, p0.y)); // no-op keep simple
                lo.x = packh(p0.x - __bfloat162float(__float2bfloat16_rn(p0.x)),
                             p0.y - __bfloat162float(__float2bfloat16_rn(p0.y)));
                lo.y = packh(p0.z - __bfloat162float(__float2bfloat16_rn(p0.z)),
                             p0.w - __bfloat162float(__float2bfloat16_rn(p0.w)));
                lo.z = packh(p1.x - __bfloat162float(__float2bfloat16_rn(p1.x)),
                             p1.y - __bfloat162float(__float2bfloat16_rn(p1.y)));
                lo.w = packh(p1.z - __bfloat162float(__float2bfloat16_rn(p1.z)),
                             p1.w - __bfloat162float(__float2bfloat16_rn(p1.w)));
                uint32_t so = r * 256 + (swu(u, r) << 4);
                *(uint4*)(sAh + so) = hi;
                *(uint4*)(sAl + so) = lo;
                (void)t;
            }
#pragma unroll
            for (int it = 0; it < 8; ++it) {
                int i2 = it * 256 + tid;
                int r = i2 >> 4, u = i2 & 15;
                size_t gs = (size_t)(krow0 + kc * 128 + r) * 1024 + hc + u * 8;
                uint32_t so = r * 256 + (swu(u, r) << 4);
                *(uint4*)(sBh + so) = *(const uint4*)(g_Vh + gs);
                *(uint4*)(sBl + so) = *(const uint4*)(g_Vl + gs);
            }
            __syncthreads();
            for (int pass = 0; pass < 3; ++pass) {
                const uint32_t Ab = (pass < 2) ? aAh : aAl;
                const uint32_t Bb = (pass == 1) ? aBl : aBh;
#pragma unroll
                for (int ks = 0; ks < 8; ++ks) {
                    uint32_t af[2][4], bfr[4][2];
#pragma unroll
                    for (int mt = 0; mt < 2; ++mt)
                        ldsm_x4(af[mt][0], af[mt][1], af[mt][2], af[mt][3],
                                Ab + (rowA0 + mt * 16) * 256 + (swu(ks * 2 + unA, rowA0) << 4));
                    int rK = ks * 16 + rowKt;
#pragma unroll
                    for (int nt = 0; nt < 4; ++nt)
                        ldsm_x2t(bfr[nt][0], bfr[nt][1],
                                 Bb + rK * 256 + (swu((wn2 >> 3) + nt, rK) << 4));
#pragma unroll
                    for (int mt = 0; mt < 2; ++mt)
#pragma unroll
                        for (int nt = 0; nt < 4; ++nt)
                            mma16816(dacc[mt][nt][0], dacc[mt][nt][1], dacc[mt][nt][2], dacc[mt][nt][3],
                                     af[mt][0], af[mt][1], af[mt][2], af[mt][3],
                                     bfr[nt][0], bfr[nt][1]);
                }
            }
        }
#pragma unroll
        for (int mt = 0; mt < 2; ++mt) {
            int r0 = wm2 + mt * 16 + (lane >> 2);
            float d0 = obsig8 / rs[r0];
            float d1 = obsig8 / rs[r0 + 8];
#pragma unroll
            for (int nt = 0; nt < 4; ++nt) {
                facc[mt][nt][0] += dacc[mt][nt][0] * d0;
                facc[mt][nt][1] += dacc[mt][nt][1] * d0;
                facc[mt][nt][2] += dacc[mt][nt][2] * d1;
                facc[mt][nt][3] += dacc[mt][nt][3] * d1;
            }
        }
    }

#pragma unroll
    for (int mt = 0; mt < 2; ++mt) {
        int r0 = wm2 + mt * 16 + (lane >> 2);
#pragma unroll
        for (int nt = 0; nt < 4; ++nt) {
            int col = wn2 + nt * 8 + ((lane & 3) << 1);
            *(float2*)&out[(size_t)(qrow0 + r0) * 128 + col]     = make_float2(facc[mt][nt][0], facc[mt][nt][1]);
            *(float2*)&out[(size_t)(qrow0 + r0 + 8) * 128 + col] = make_float2(facc[mt][nt][2], facc[mt][nt][3]);
        }
    }
}

// =====================================================================
extern "C" void kernel_launch(void* const* d_in, const int* in_sizes, int n_in,
                              void* d_out, int out_size)
{
    const float* x    = (const float*)d_in[0];
    const float* wq   = (const float*)d_in[1];
    const float* bq   = (const float*)d_in[2];
    const float* wk   = (const float*)d_in[3];
    const float* bk   = (const float*)d_in[4];
    const float* wv   = (const float*)d_in[5];
    const float* bv   = (const float*)d_in[6];
    const float* beta = (const float*)d_in[7];
    float* out = (float*)d_out;

    static int attr_set = 0;
    if (!attr_set) {
        cudaFuncSetAttribute(k_attn_mma, cudaFuncAttributeMaxDynamicSharedMemorySize, 231424);
        cudaFuncSetAttribute(k_proj_mma, cudaFuncAttributeMaxDynamicSharedMemorySize, 65536);
        attr_set = 1;
    }

    k_splitX<<<32768, 256>>>(x);
    k_splitW<<<dim3(32, 32), 256>>>(wq, 0);
    k_splitW<<<dim3(32, 32), 256>>>(wk, 1);
    k_splitW<<<dim3(32, 32), 256>>>(wv, 2);
    dim3 gp(8, 256);
    k_proj_mma<<<gp, 256, 65536>>>(bq, 0);
    k_proj_mma<<<gp, 256, 65536>>>(bk, 1);
    k_proj_mma<<<gp, 256, 65536>>>(bv, 2);
    k_kvouter<<<512, 256>>>();
    k_prefix<<<32, 256>>>();
    k_attn_mma<<<512, 256, 231424>>>(beta, out);
}

// round 7
// speedup vs baseline: 2.4555x; 1.1333x over previous
#include <cuda_runtime.h>
#include <cuda_bf16.h>
#include <cstdint>

typedef unsigned long long ull_t;

// ---------- packed fp32x2 helpers ----------
__device__ __forceinline__ ull_t pk2(float x, float y){
    ull_t r; asm("mov.b64 %0, {%1,%2};" : "=l"(r) : "f"(x), "f"(y)); return r;
}
__device__ __forceinline__ void fma2(ull_t &d, ull_t a, ull_t b){
    asm("fma.rn.f32x2 %0, %1, %2, %0;" : "+l"(d) : "l"(a), "l"(b));
}
__device__ __forceinline__ float2 upk2(ull_t v){
    float lo, hi; asm("mov.b64 {%0,%1}, %2;" : "=f"(lo), "=f"(hi) : "l"(v));
    return make_float2(lo, hi);
}
__device__ __forceinline__ float elup1(float x){ return x > 0.f ? x + 1.f : __expf(x); }

#define FMA8x4(ACCROW, AV, B01, B23) do { ull_t ad_ = pk2((AV),(AV)); \
    fma2((ACCROW)[0], ad_, (B01).x); fma2((ACCROW)[1], ad_, (B01).y); \
    fma2((ACCROW)[2], ad_, (B23).x); fma2((ACCROW)[3], ad_, (B23).y); } while(0)

// ---------- warp MMA / async helpers ----------
__device__ __forceinline__ uint32_t smem_u32(const void* p){
    uint32_t a;
    asm("{ .reg .u64 t; cvta.to.shared.u64 t, %1; cvt.u32.u64 %0, t; }" : "=r"(a) : "l"(p));
    return a;
}
__device__ __forceinline__ void cpa16(uint32_t smaddr, const void* g){
    asm volatile("cp.async.cg.shared.global [%0], [%1], 16;" :: "r"(smaddr), "l"(g));
}
#define CP_COMMIT() asm volatile("cp.async.commit_group;" ::: "memory")
#define CP_WAIT2()  asm volatile("cp.async.wait_group 2;" ::: "memory")
__device__ __forceinline__ void ldsm_x4(uint32_t &r0, uint32_t &r1, uint32_t &r2, uint32_t &r3, uint32_t addr){
    asm volatile("ldmatrix.sync.aligned.m8n8.x4.shared.b16 {%0,%1,%2,%3}, [%4];"
        : "=r"(r0), "=r"(r1), "=r"(r2), "=r"(r3) : "r"(addr));
}
__device__ __forceinline__ void ldsm_x2(uint32_t &r0, uint32_t &r1, uint32_t addr){
    asm volatile("ldmatrix.sync.aligned.m8n8.x2.shared.b16 {%0,%1}, [%2];"
        : "=r"(r0), "=r"(r1) : "r"(addr));
}
__device__ __forceinline__ void ldsm_x2t(uint32_t &r0, uint32_t &r1, uint32_t addr){
    asm volatile("ldmatrix.sync.aligned.m8n8.x2.trans.shared.b16 {%0,%1}, [%2];"
        : "=r"(r0), "=r"(r1) : "r"(addr));
}
__device__ __forceinline__ void mma16816(float &c0, float &c1, float &c2, float &c3,
                                         uint32_t a0, uint32_t a1, uint32_t a2, uint32_t a3,
                                         uint32_t b0, uint32_t b1){
    asm volatile("mma.sync.aligned.m16n8k16.row.col.f32.bf16.bf16.f32 "
        "{%0,%1,%2,%3}, {%4,%5,%6,%7}, {%8,%9}, {%0,%1,%2,%3};"
        : "+f"(c0), "+f"(c1), "+f"(c2), "+f"(c3)
        : "r"(a0), "r"(a1), "r"(a2), "r"(a3), "r"(b0), "r"(b1));
}
__device__ __forceinline__ uint32_t swu(int u, int r){ return (uint32_t)((u & 8) | ((u & 7) ^ (r & 7))); }
__device__ __forceinline__ uint32_t packh(float a, float b){
    __nv_bfloat162 t = __halves2bfloat162(__float2bfloat16_rn(a), __float2bfloat16_rn(b));
    return *(uint32_t*)&t;
}
__device__ __forceinline__ void bsplit2(__nv_bfloat16* H, __nv_bfloat16* L, size_t off, float2 v){
    __nv_bfloat16 hx = __float2bfloat16_rn(v.x), hy = __float2bfloat16_rn(v.y);
    __nv_bfloat16 lx = __float2bfloat16_rn(v.x - __bfloat162float(hx));
    __nv_bfloat16 ly = __float2bfloat16_rn(v.y - __bfloat162float(hy));
    *(__nv_bfloat162*)(H + off) = __halves2bfloat162(hx, hy);
    *(__nv_bfloat162*)(L + off) = __halves2bfloat162(lx, ly);
}
__device__ __forceinline__ float4 ld4hl(const __nv_bfloat16* H, const __nv_bfloat16* L, size_t off){
    uint2 h = *(const uint2*)(H + off), l = *(const uint2*)(L + off);
    float2 fh0 = __bfloat1622float2(*(__nv_bfloat162*)&h.x);
    float2 fh1 = __bfloat1622float2(*(__nv_bfloat162*)&h.y);
    float2 fl0 = __bfloat1622float2(*(__nv_bfloat162*)&l.x);
    float2 fl1 = __bfloat1622float2(*(__nv_bfloat162*)&l.y);
    return make_float4(fh0.x + fl0.x, fh0.y + fl0.y, fh1.x + fl1.x, fh1.y + fl1.y);
}

// ---------- dims: B=4, S=8192, D=1024, H=8, dk=dv=128, SEG=512, nseg=16 ----------

// ---------- device scratch ----------
__device__ float g_P[8388608];
__device__ float g_Zseg[65536];
__device__ float g_Z[65536];
__device__ __nv_bfloat16 g_Xh[33554432];
__device__ __nv_bfloat16 g_Xl[33554432];
__device__ __nv_bfloat16 g_Wth[3145728];
__device__ __nv_bfloat16 g_Wtl[3145728];
__device__ __nv_bfloat16 g_Qh[33554432];
__device__ __nv_bfloat16 g_Ql[33554432];
__device__ __nv_bfloat16 g_Kh[33554432];
__device__ __nv_bfloat16 g_Kl[33554432];
__device__ __nv_bfloat16 g_Vh[33554432];
__device__ __nv_bfloat16 g_Vl[33554432];
__device__ __nv_bfloat16 g_Memh[8388608];
__device__ __nv_bfloat16 g_Meml[8388608];

// =====================================================================
// S1: split X into bf16 hi/lo
// =====================================================================
__global__ __launch_bounds__(256) void k_splitX(const float* __restrict__ x)
{
    size_t i = ((size_t)blockIdx.x * 256 + threadIdx.x) * 4;
    float4 v = *(const float4*)(x + i);
    bsplit2(g_Xh, g_Xl, i,     make_float2(v.x, v.y));
    bsplit2(g_Xh, g_Xl, i + 2, make_float2(v.z, v.w));
}

// =====================================================================
// S2: transpose + split W[k][n] -> Wt[n][k] bf16 hi/lo
// =====================================================================
__global__ __launch_bounds__(256) void k_splitW(const float* __restrict__ w, int which)
{
    __shared__ float t[32][33];
    const int bx = blockIdx.x << 5, by = blockIdx.y << 5;
    const int tx = threadIdx.x & 31, ty = threadIdx.x >> 5;
#pragma unroll
    for (int r = 0; r < 4; ++r)
        t[ty * 4 + r][tx] = w[(size_t)(by + ty * 4 + r) * 1024 + bx + tx];
    __syncthreads();
    __nv_bfloat16* Ht = g_Wth + (size_t)which * 1048576;
    __nv_bfloat16* Lt = g_Wtl + (size_t)which * 1048576;
#pragma unroll
    for (int r = 0; r < 4; ++r) {
        int n = bx + ty * 4 + r, k = by + tx;
        float val = t[tx][ty * 4 + r];
        __nv_bfloat16 h = __float2bfloat16_rn(val);
        __nv_bfloat16 l = __float2bfloat16_rn(val - __bfloat162float(h));
        Ht[(size_t)n * 1024 + k] = h;
        Lt[(size_t)n * 1024 + k] = l;
    }
}

// =====================================================================
// K1: projection GEMM — cp.async 3-stage pipeline, interleaved hi/lo.
//     Per K64 chunk: load Xh/Xl/Wh/Wl tiles; mma AhBh + AhBl + AlBh.
//     Stage = 4 tiles x 16KB = 64KB; 3 stages = 192KB smem.
// =====================================================================
__global__ __launch_bounds__(256, 1) void k_proj_mma(const float* __restrict__ bias, int which)
{
    extern __shared__ __align__(128) char sm_raw[];
    const uint32_t smbase = smem_u32(sm_raw);

    __nv_bfloat16* Hd = (which == 0) ? g_Qh : ((which == 1) ? g_Kh : g_Vh);
    __nv_bfloat16* Ld = (which == 0) ? g_Ql : ((which == 1) ? g_Kl : g_Vl);
    const __nv_bfloat16* Wh = g_Wth + (size_t)which * 1048576;
    const __nv_bfloat16* Wl = g_Wtl + (size_t)which * 1048576;

    const int tid = threadIdx.x, lane = tid & 31, wid = tid >> 5;
    const int wm = (wid >> 2) * 64, wn = (wid & 3) * 32;
    const int row0 = blockIdx.y << 7, col0 = blockIdx.x << 7;

    const int rowA = wm + (lane & 15);
    const int rA7 = rowA & 7;
    const int unA = lane >> 4;
    const int rowB = wn + (lane & 7);
    const int rB7 = lane & 7;
    const int unB = (lane >> 3) & 1;

    // loader precompute
    const int lr = tid >> 3, lu = tid & 7;   // idx = it*256+tid -> r = lr + it*32, u = lu

    float cf[4][4][4];
#pragma unroll
    for (int mt = 0; mt < 4; ++mt)
#pragma unroll
        for (int nt = 0; nt < 4; ++nt)
#pragma unroll
            for (int q = 0; q < 4; ++q) cf[mt][nt][q] = 0.f;

    // chunk loader: 16 cp.async of 16B per thread
    auto load_chunk = [&](int c, int stage) {
        const int k0 = c << 6;
        const uint32_t st = smbase + stage * 65536;
#pragma unroll
        for (int it = 0; it < 4; ++it) {
            int r = lr + it * 32;
            size_t ga = (size_t)(row0 + r) * 1024 + k0 + lu * 8;
            size_t gb = (size_t)(col0 + r) * 1024 + k0 + lu * 8;
            uint32_t so = r * 128 + ((lu ^ (r & 7)) << 4);
            cpa16(st + so,         g_Xh + ga);
            cpa16(st + 16384 + so, g_Xl + ga);
            cpa16(st + 32768 + so, Wh + gb);
            cpa16(st + 49152 + so, Wl + gb);
        }
    };

    load_chunk(0, 0); CP_COMMIT();
    load_chunk(1, 1); CP_COMMIT();

    for (int c = 0; c < 16; ++c) {
        if (c + 2 < 16) load_chunk(c + 2, (c + 2) % 3);
        CP_COMMIT();
        CP_WAIT2();
        __syncthreads();
        const uint32_t st = smbase + (c % 3) * 65536;
#pragma unroll
        for (int ks = 0; ks < 4; ++ks) {
            uint32_t ah[4][4], al[4][4], bh[4][2], bl[4][2];
#pragma unroll
            for (int mt = 0; mt < 4; ++mt) {
                uint32_t off = (rowA + mt * 16) * 128 + ((((ks << 1) + unA) ^ rA7) << 4);
                ldsm_x4(ah[mt][0], ah[mt][1], ah[mt][2], ah[mt][3], st + off);
                ldsm_x4(al[mt][0], al[mt][1], al[mt][2], al[mt][3], st + 16384 + off);
            }
#pragma unroll
            for (int nt = 0; nt < 4; ++nt) {
                uint32_t off = (rowB + nt * 8) * 128 + ((((ks << 1) + unB) ^ rB7) << 4);
                ldsm_x2(bh[nt][0], bh[nt][1], st + 32768 + off);
                ldsm_x2(bl[nt][0], bl[nt][1], st + 49152 + off);
            }
#pragma unroll
            for (int mt = 0; mt < 4; ++mt)
#pragma unroll
                for (int nt = 0; nt < 4; ++nt) {
                    mma16816(cf[mt][nt][0], cf[mt][nt][1], cf[mt][nt][2], cf[mt][nt][3],
                             ah[mt][0], ah[mt][1], ah[mt][2], ah[mt][3], bh[nt][0], bh[nt][1]);
                    mma16816(cf[mt][nt][0], cf[mt][nt][1], cf[mt][nt][2], cf[mt][nt][3],
                             ah[mt][0], ah[mt][1], ah[mt][2], ah[mt][3], bl[nt][0], bl[nt][1]);
                    mma16816(cf[mt][nt][0], cf[mt][nt][1], cf[mt][nt][2], cf[mt][nt][3],
                             al[mt][0], al[mt][1], al[mt][2], al[mt][3], bh[nt][0], bh[nt][1]);
                }
        }
        __syncthreads();
    }

    // epilogue: bias + bf16 hi/lo splits only
#pragma unroll
    for (int mt = 0; mt < 4; ++mt) {
        const int r0 = row0 + wm + mt * 16 + (lane >> 2);
#pragma unroll
        for (int nt = 0; nt < 4; ++nt) {
            const int ccol = col0 + wn + nt * 8 + ((lane & 3) << 1);
            const float2 bv = *(const float2*)&bias[ccol];
            float2 v0 = make_float2(cf[mt][nt][0] + bv.x, cf[mt][nt][1] + bv.y);
            float2 v1 = make_float2(cf[mt][nt][2] + bv.x, cf[mt][nt][3] + bv.y);
            size_t o0 = (size_t)r0 * 1024 + ccol;
            size_t o1 = o0 + 8 * 1024;
            bsplit2(Hd, Ld, o0, v0);
            bsplit2(Hd, Ld, o1, v1);
        }
    }
}

// =====================================================================
// K2: per (b,h,seg): P = (elu(K)+1)^T @ V  [128x128], Zseg = 512*colsum
//     (reads bf16 hi/lo splits; K = Kh+Kl etc.)
// =====================================================================
__global__ __launch_bounds__(256) void k_kvouter()
{
    const int idx = blockIdx.x;
    const int b = idx >> 7, h = (idx >> 4) & 7, seg = idx & 15;
    __shared__ __align__(16) float sks[16][128];
    __shared__ __align__(16) float vvs[16][128];
    const int tid = threadIdx.x, tx = tid & 15, ty = tid >> 4;
    const int lr = tid >> 5, c4 = (tid & 31) << 2;

    ull_t acc[8][4];
#pragma unroll
    for (int i = 0; i < 8; ++i)
#pragma unroll
        for (int j = 0; j < 4; ++j) acc[i][j] = 0ull;
    float zacc[8] = {0.f,0.f,0.f,0.f,0.f,0.f,0.f,0.f};

    const size_t rowbase = (size_t)(b * 8192 + seg * 512) * 1024 + h * 128;

    for (int l0 = 0; l0 < 512; l0 += 16) {
        float4 k0v = ld4hl(g_Kh, g_Kl, rowbase + (size_t)(l0 + lr) * 1024 + c4);
        float4 k1v = ld4hl(g_Kh, g_Kl, rowbase + (size_t)(l0 + lr + 8) * 1024 + c4);
        float4 v0v = ld4hl(g_Vh, g_Vl, rowbase + (size_t)(l0 + lr) * 1024 + c4);
        float4 v1v = ld4hl(g_Vh, g_Vl, rowbase + (size_t)(l0 + lr + 8) * 1024 + c4);
        k0v.x = elup1(k0v.x); k0v.y = elup1(k0v.y); k0v.z = elup1(k0v.z); k0v.w = elup1(k0v.w);
        k1v.x = elup1(k1v.x); k1v.y = elup1(k1v.y); k1v.z = elup1(k1v.z); k1v.w = elup1(k1v.w);
        __syncthreads();
        *(float4*)&sks[lr][c4]     = k0v;
        *(float4*)&sks[lr + 8][c4] = k1v;
        *(float4*)&vvs[lr][c4]     = v0v;
        *(float4*)&vvs[lr + 8][c4] = v1v;
        __syncthreads();
#pragma unroll
        for (int l = 0; l < 16; ++l) {
            float4 a0 = *(const float4*)&sks[l][ty * 8];
            float4 a1 = *(const float4*)&sks[l][ty * 8 + 4];
            ulonglong2 b01 = *(const ulonglong2*)&vvs[l][tx * 8];
            ulonglong2 b23 = *(const ulonglong2*)&vvs[l][tx * 8 + 4];
            if (tx == 0) {
                zacc[0] += a0.x; zacc[1] += a0.y; zacc[2] += a0.z; zacc[3] += a0.w;
                zacc[4] += a1.x; zacc[5] += a1.y; zacc[6] += a1.z; zacc[7] += a1.w;
            }
            FMA8x4(acc[0], a0.x, b01, b23);
            FMA8x4(acc[1], a0.y, b01, b23);
            FMA8x4(acc[2], a0.z, b01, b23);
            FMA8x4(acc[3], a0.w, b01, b23);
            FMA8x4(acc[4], a1.x, b01, b23);
            FMA8x4(acc[5], a1.y, b01, b23);
            FMA8x4(acc[6], a1.z, b01, b23);
            FMA8x4(acc[7], a1.w, b01, b23);
        }
    }
    const size_t pbase = (size_t)idx * 16384;
#pragma unroll
    for (int i = 0; i < 8; ++i) {
        size_t rb = pbase + (size_t)(ty * 8 + i) * 128 + tx * 8;
#pragma unroll
        for (int jp = 0; jp < 4; ++jp) {
            float2 v = upk2(acc[i][jp]);
            g_P[rb + jp * 2]     = v.x;
            g_P[rb + jp * 2 + 1] = v.y;
        }
    }
    if (tx == 0) {
#pragma unroll
        for (int i = 0; i < 8; ++i)
            g_Zseg[idx * 128 + ty * 8 + i] = 512.f * zacc[i];
    }
}

// =====================================================================
// K3: inclusive prefix over seg; writes bf16 hi/lo Mem splits + Z
// =====================================================================
__global__ __launch_bounds__(256) void k_prefix()
{
    const int bh = blockIdx.x;
    const int tid = threadIdx.x;
    float acc[64];
#pragma unroll
    for (int u = 0; u < 64; ++u) acc[u] = 0.f;
    float zacc = 0.f;
    for (int seg = 0; seg < 16; ++seg) {
        const size_t base = ((size_t)bh * 16 + seg) * 16384;
#pragma unroll
        for (int u = 0; u < 64; ++u) {
            acc[u] += g_P[base + u * 256 + tid];
            float v = acc[u];
            __nv_bfloat16 h = __float2bfloat16_rn(v);
            __nv_bfloat16 l = __float2bfloat16_rn(v - __bfloat162float(h));
            g_Memh[base + u * 256 + tid] = h;
            g_Meml[base + u * 256 + tid] = l;
        }
        if (tid < 128) {
            zacc += g_Zseg[(bh * 16 + seg) * 128 + tid];
            g_Z[(bh * 16 + seg) * 128 + tid] = zacc;
        }
    }
}

// =====================================================================
// K4: mma.sync attention. CTA=(b,seg,qt64), 8 warps, loops 8 heads.
// =====================================================================
__global__ __launch_bounds__(256, 1) void k_attn_mma(const float* __restrict__ beta,
                                                     float* __restrict__ out)
{
    extern __shared__ __align__(16) char smraw[];
    float* Sc = (float*)smraw;                       // 132096 B
    char* sAh = smraw + 132096;                      // 16384
    char* sAl = sAh + 16384;                         // 16384
    char* sBh = sAl + 16384;                         // 32768
    char* sBl = sBh + 32768;                         // 32768
    float* zs  = (float*)(sBl + 32768);              // 128
    float* rs  = zs + 128;                           // 64
    float* den = rs + 64;                            // 64
    const uint32_t aAh = smem_u32(sAh), aAl = smem_u32(sAl);
    const uint32_t aBh = smem_u32(sBh), aBl = smem_u32(sBl);

    const int idx = blockIdx.x;                      // b*128 + seg*8 + qt
    const int b = idx >> 7, seg = (idx >> 3) & 15, qt = idx & 7;
    const int tid = threadIdx.x, lane = tid & 31, wid = tid >> 5;
    const int wm2 = (wid >> 2) * 32, wn2 = (wid & 3) * 32;
    const int qrow0 = b * 8192 + seg * 512 + qt * 64;
    const int krow0 = b * 8192 + seg * 512;
    const float bsig = 1.f / (1.f + __expf(-beta[0]));
    const float bsig8 = bsig * 0.125f, obsig8 = (1.f - bsig) * 0.125f;
    const float scale = 0.088388347648318447f;

    const int rowA0 = wm2 + (lane & 15);
    const int unA = lane >> 4;
    const int rowBn = wn2 + (lane & 7);
    const int unB = (lane >> 3) & 1;
    const int rowKt = (lane & 7) + ((lane >> 3) & 1) * 8;
    const int srow = tid >> 2, spart = tid & 3;

    float facc[2][4][4];
#pragma unroll
    for (int mt = 0; mt < 2; ++mt)
#pragma unroll
        for (int nt = 0; nt < 4; ++nt)
#pragma unroll
            for (int q = 0; q < 4; ++q) facc[mt][nt][q] = 0.f;

    for (int h = 0; h < 8; ++h) {
        const int hc = h * 128;
        __syncthreads();
#pragma unroll
        for (int it = 0; it < 4; ++it) {
            int i2 = it * 256 + tid;
            int r = i2 >> 4, u = i2 & 15;
            size_t gs = (size_t)(qrow0 + r) * 1024 + hc + u * 8;
            uint32_t so = r * 256 + (swu(u, r) << 4);
            *(uint4*)(sAh + so) = *(const uint4*)(g_Qh + gs);
            *(uint4*)(sAl + so) = *(const uint4*)(g_Ql + gs);
        }
        if (tid < 128)
            zs[tid] = g_Z[((size_t)(b * 8 + h) * 16 + seg) * 128 + tid];

        // ---- scores: 4 key chunks of 128 ----
        for (int kc = 0; kc < 4; ++kc) {
            __syncthreads();
#pragma unroll
            for (int it = 0; it < 8; ++it) {
                int i2 = it * 256 + tid;
                int r = i2 >> 4, u = i2 & 15;
                size_t gs = (size_t)(krow0 + kc * 128 + r) * 1024 + hc + u * 8;
                uint32_t so = r * 256 + (swu(u, r) << 4);
                *(uint4*)(sBh + so) = *(const uint4*)(g_Kh + gs);
                *(uint4*)(sBl + so) = *(const uint4*)(g_Kl + gs);
            }
            __syncthreads();
            float acc[2][4][4];
#pragma unroll
            for (int mt = 0; mt < 2; ++mt)
#pragma unroll
                for (int nt = 0; nt < 4; ++nt)
#pragma unroll
                    for (int q = 0; q < 4; ++q) acc[mt][nt][q] = 0.f;
            for (int pass = 0; pass < 3; ++pass) {
                const uint32_t Ab = (pass < 2) ? aAh : aAl;
                const uint32_t Bb = (pass == 1) ? aBl : aBh;
#pragma unroll
                for (int ks = 0; ks < 8; ++ks) {
                    uint32_t af[2][4], bfr[4][2];
#pragma unroll
                    for (int mt = 0; mt < 2; ++mt)
                        ldsm_x4(af[mt][0], af[mt][1], af[mt][2], af[mt][3],
                                Ab + (rowA0 + mt * 16) * 256 + (swu(ks * 2 + unA, rowA0) << 4));
#pragma unroll
                    for (int nt = 0; nt < 4; ++nt)
                        ldsm_x2(bfr[nt][0], bfr[nt][1],
                                Bb + (rowBn + nt * 8) * 256 + (swu(ks * 2 + unB, rowBn) << 4));
#pragma unroll
                    for (int mt = 0; mt < 2; ++mt)
#pragma unroll
                        for (int nt = 0; nt < 4; ++nt)
                            mma16816(acc[mt][nt][0], acc[mt][nt][1], acc[mt][nt][2], acc[mt][nt][3],
                                     af[mt][0], af[mt][1], af[mt][2], af[mt][3],
                                     bfr[nt][0], bfr[nt][1]);
                }
            }
#pragma unroll
            for (int mt = 0; mt < 2; ++mt) {
                int r0 = wm2 + mt * 16 + (lane >> 2);
#pragma unroll
                for (int nt = 0; nt < 4; ++nt) {
                    int cc = kc * 128 + wn2 + nt * 8 + ((lane & 3) << 1);
                    *(float2*)&Sc[r0 * 516 + cc]       = make_float2(acc[mt][nt][0] * scale, acc[mt][nt][1] * scale);
                    *(float2*)&Sc[(r0 + 8) * 516 + cc] = make_float2(acc[mt][nt][2] * scale, acc[mt][nt][3] * scale);
                }
            }
        }
        __syncthreads();
        // ---- softmax ----
        {
            float* rowp = &Sc[srow * 516 + spart * 128];
            float m = -1e30f;
#pragma unroll 8
            for (int j = 0; j < 128; ++j) m = fmaxf(m, rowp[j]);
            m = fmaxf(m, __shfl_xor_sync(0xffffffffu, m, 1));
            m = fmaxf(m, __shfl_xor_sync(0xffffffffu, m, 2));
            float s = 0.f;
#pragma unroll 8
            for (int j = 0; j < 128; ++j) { float e = __expf(rowp[j] - m); rowp[j] = e; s += e; }
            s += __shfl_xor_sync(0xffffffffu, s, 1);
            s += __shfl_xor_sync(0xffffffffu, s, 2);
            if (spart == 0) rs[srow] = s;
        }
        // ---- sq transform + exact den ----
        {
            float da = 0.f;
#pragma unroll 4
            for (int j = 0; j < 32; ++j) {
                int c = spart * 32 + j;
                uint32_t bo = srow * 256 + (swu(c >> 3, srow) << 4) + ((c & 7) << 1);
                float qh = __bfloat162float(*(__nv_bfloat16*)(sAh + bo));
                float ql = __bfloat162float(*(__nv_bfloat16*)(sAl + bo));
                float sq = elup1(qh + ql);
                da += sq * zs[c];
                __nv_bfloat16 hh = __float2bfloat16_rn(sq);
                __nv_bfloat16 ll = __float2bfloat16_rn(sq - __bfloat162float(hh));
                *(__nv_bfloat16*)(sAh + bo) = hh;
                *(__nv_bfloat16*)(sAl + bo) = ll;
            }
            da += __shfl_xor_sync(0xffffffffu, da, 1);
            da += __shfl_xor_sync(0xffffffffu, da, 2);
            if (spart == 0) den[srow] = da;
        }
        __syncthreads();
        // ---- retrieval ----
#pragma unroll
        for (int it = 0; it < 8; ++it) {
            int i2 = it * 256 + tid;
            int r = i2 >> 4, u = i2 & 15;
            size_t ms = ((size_t)(b * 8 + h) * 16 + seg) * 16384 + r * 128 + u * 8;
            uint32_t so = r * 256 + (swu(u, r) << 4);
            *(uint4*)(sBh + so) = *(const uint4*)(g_Memh + ms);
            *(uint4*)(sBl + so) = *(const uint4*)(g_Meml + ms);
        }
        __syncthreads();
        {
            float acc[2][4][4];
#pragma unroll
            for (int mt = 0; mt < 2; ++mt)
#pragma unroll
                for (int nt = 0; nt < 4; ++nt)
#pragma unroll
                    for (int q = 0; q < 4; ++q) acc[mt][nt][q] = 0.f;
            for (int pass = 0; pass < 3; ++pass) {
                const uint32_t Ab = (pass < 2) ? aAh : aAl;
                const uint32_t Bb = (pass == 1) ? aBl : aBh;
#pragma unroll
                for (int ks = 0; ks < 8; ++ks) {
                    uint32_t af[2][4], bfr[4][2];
#pragma unroll
                    for (int mt = 0; mt < 2; ++mt)
                        ldsm_x4(af[mt][0], af[mt][1], af[mt][2], af[mt][3],
                                Ab + (rowA0 + mt * 16) * 256 + (swu(ks * 2 + unA, rowA0) << 4));
                    int rK = ks * 16 + rowKt;
#pragma unroll
                    for (int nt = 0; nt < 4; ++nt)
                        ldsm_x2t(bfr[nt][0], bfr[nt][1],
                                 Bb + rK * 256 + (swu((wn2 >> 3) + nt, rK) << 4));
#pragma unroll
                    for (int mt = 0; mt < 2; ++mt)
#pragma unroll
                        for (int nt = 0; nt < 4; ++nt)
                            mma16816(acc[mt][nt][0], acc[mt][nt][1], acc[mt][nt][2], acc[mt][nt][3],
                                     af[mt][0], af[mt][1], af[mt][2], af[mt][3],
                                     bfr[nt][0], bfr[nt][1]);
                }
            }
#pragma unroll
            for (int mt = 0; mt < 2; ++mt) {
                int r0 = wm2 + mt * 16 + (lane >> 2);
                float m0 = bsig8 / (den[r0] + 1e-5f);
                float m1 = bsig8 / (den[r0 + 8] + 1e-5f);
#pragma unroll
                for (int nt = 0; nt < 4; ++nt) {
                    facc[mt][nt][0] += acc[mt][nt][0] * m0;
                    facc[mt][nt][1] += acc[mt][nt][1] * m0;
                    facc[mt][nt][2] += acc[mt][nt][2] * m1;
                    facc[mt][nt][3] += acc[mt][nt][3] * m1;
                }
            }
        }
        // ---- PV ----
        float dacc[2][4][4];
#pragma unroll
        for (int mt = 0; mt < 2; ++mt)
#pragma unroll
            for (int nt = 0; nt < 4; ++nt)
#pragma unroll
                for (int q = 0; q < 4; ++q) dacc[mt][nt][q] = 0.f;
        for (int kc = 0; kc < 4; ++kc) {
            __syncthreads();
#pragma unroll
            for (int it = 0; it < 4; ++it) {
                int i2 = it * 256 + tid;
                int r = i2 >> 4, u = i2 & 15;
                const float* sp = &Sc[r * 516 + kc * 128 + u * 8];
                float4 p0 = *(const float4*)sp, p1 = *(const float4*)(sp + 4);
                uint4 hi, lo;
                hi.x = packh(p0.x, p0.y); hi.y = packh(p0.z, p0.w);
                hi.z = packh(p1.x, p1.y); hi.w = packh(p1.z, p1.w);
                lo.x = packh(p0.x - __bfloat162float(__float2bfloat16_rn(p0.x)),
                             p0.y - __bfloat162float(__float2bfloat16_rn(p0.y)));
                lo.y = packh(p0.z - __bfloat162float(__float2bfloat16_rn(p0.z)),
                             p0.w - __bfloat162float(__float2bfloat16_rn(p0.w)));
                lo.z = packh(p1.x - __bfloat162float(__float2bfloat16_rn(p1.x)),
                             p1.y - __bfloat162float(__float2bfloat16_rn(p1.y)));
                lo.w = packh(p1.z - __bfloat162float(__float2bfloat16_rn(p1.z)),
                             p1.w - __bfloat162float(__float2bfloat16_rn(p1.w)));
                uint32_t so = r * 256 + (swu(u, r) << 4);
                *(uint4*)(sAh + so) = hi;
                *(uint4*)(sAl + so) = lo;
            }
#pragma unroll
            for (int it = 0; it < 8; ++it) {
                int i2 = it * 256 + tid;
                int r = i2 >> 4, u = i2 & 15;
                size_t gs = (size_t)(krow0 + kc * 128 + r) * 1024 + hc + u * 8;
                uint32_t so = r * 256 + (swu(u, r) << 4);
                *(uint4*)(sBh + so) = *(const uint4*)(g_Vh + gs);
                *(uint4*)(sBl + so) = *(const uint4*)(g_Vl + gs);
            }
            __syncthreads();
            for (int pass = 0; pass < 3; ++pass) {
                const uint32_t Ab = (pass < 2) ? aAh : aAl;
                const uint32_t Bb = (pass == 1) ? aBl : aBh;
#pragma unroll
                for (int ks = 0; ks < 8; ++ks) {
                    uint32_t af[2][4], bfr[4][2];
#pragma unroll
                    for (int mt = 0; mt < 2; ++mt)
                        ldsm_x4(af[mt][0], af[mt][1], af[mt][2], af[mt][3],
                                Ab + (rowA0 + mt * 16) * 256 + (swu(ks * 2 + unA, rowA0) << 4));
                    int rK = ks * 16 + rowKt;
#pragma unroll
                    for (int nt = 0; nt < 4; ++nt)
                        ldsm_x2t(bfr[nt][0], bfr[nt][1],
                                 Bb + rK * 256 + (swu((wn2 >> 3) + nt, rK) << 4));
#pragma unroll
                    for (int mt = 0; mt < 2; ++mt)
#pragma unroll
                        for (int nt = 0; nt < 4; ++nt)
                            mma16816(dacc[mt][nt][0], dacc[mt][nt][1], dacc[mt][nt][2], dacc[mt][nt][3],
                                     af[mt][0], af[mt][1], af[mt][2], af[mt][3],
                                     bfr[nt][0], bfr[nt][1]);
                }
            }
        }
#pragma unroll
        for (int mt = 0; mt < 2; ++mt) {
            int r0 = wm2 + mt * 16 + (lane >> 2);
            float d0 = obsig8 / rs[r0];
            float d1 = obsig8 / rs[r0 + 8];
#pragma unroll
            for (int nt = 0; nt < 4; ++nt) {
                facc[mt][nt][0] += dacc[mt][nt][0] * d0;
                facc[mt][nt][1] += dacc[mt][nt][1] * d0;
                facc[mt][nt][2] += dacc[mt][nt][2] * d1;
                facc[mt][nt][3] += dacc[mt][nt][3] * d1;
            }
        }
    }

#pragma unroll
    for (int mt = 0; mt < 2; ++mt) {
        int r0 = wm2 + mt * 16 + (lane >> 2);
#pragma unroll
        for (int nt = 0; nt < 4; ++nt) {
            int col = wn2 + nt * 8 + ((lane & 3) << 1);
            *(float2*)&out[(size_t)(qrow0 + r0) * 128 + col]     = make_float2(facc[mt][nt][0], facc[mt][nt][1]);
            *(float2*)&out[(size_t)(qrow0 + r0 + 8) * 128 + col] = make_float2(facc[mt][nt][2], facc[mt][nt][3]);
        }
    }
}

// =====================================================================
extern "C" void kernel_launch(void* const* d_in, const int* in_sizes, int n_in,
                              void* d_out, int out_size)
{
    const float* x    = (const float*)d_in[0];
    const float* wq   = (const float*)d_in[1];
    const float* bq   = (const float*)d_in[2];
    const float* wk   = (const float*)d_in[3];
    const float* bk   = (const float*)d_in[4];
    const float* wv   = (const float*)d_in[5];
    const float* bv   = (const float*)d_in[6];
    const float* beta = (const float*)d_in[7];
    float* out = (float*)d_out;

    static int attr_set = 0;
    if (!attr_set) {
        cudaFuncSetAttribute(k_attn_mma, cudaFuncAttributeMaxDynamicSharedMemorySize, 231424);
        cudaFuncSetAttribute(k_proj_mma, cudaFuncAttributeMaxDynamicSharedMemorySize, 196608);
        attr_set = 1;
    }

    k_splitX<<<32768, 256>>>(x);
    k_splitW<<<dim3(32, 32), 256>>>(wq, 0);
    k_splitW<<<dim3(32, 32), 256>>>(wk, 1);
    k_splitW<<<dim3(32, 32), 256>>>(wv, 2);
    dim3 gp(8, 256);
    k_proj_mma<<<gp, 256, 196608>>>(bq, 0);
    k_proj_mma<<<gp, 256, 196608>>>(bk, 1);
    k_proj_mma<<<gp, 256, 196608>>>(bv, 2);
    k_kvouter<<<512, 256>>>();
    k_prefix<<<32, 256>>>();
    k_attn_mma<<<512, 256, 231424>>>(beta, out);
}

// round 8
// speedup vs baseline: 2.4907x; 1.0143x over previous
#include <cuda_runtime.h>
#include <cuda_bf16.h>
#include <cstdint>

typedef unsigned long long ull_t;

// ---------- packed fp32x2 helpers ----------
__device__ __forceinline__ ull_t pk2(float x, float y){
    ull_t r; asm("mov.b64 %0, {%1,%2};" : "=l"(r) : "f"(x), "f"(y)); return r;
}
__device__ __forceinline__ void fma2(ull_t &d, ull_t a, ull_t b){
    asm("fma.rn.f32x2 %0, %1, %2, %0;" : "+l"(d) : "l"(a), "l"(b));
}
__device__ __forceinline__ float2 upk2(ull_t v){
    float lo, hi; asm("mov.b64 {%0,%1}, %2;" : "=f"(lo), "=f"(hi) : "l"(v));
    return make_float2(lo, hi);
}
__device__ __forceinline__ float elup1(float x){ return x > 0.f ? x + 1.f : __expf(x); }

#define FMA8x4(ACCROW, AV, B01, B23) do { ull_t ad_ = pk2((AV),(AV)); \
    fma2((ACCROW)[0], ad_, (B01).x); fma2((ACCROW)[1], ad_, (B01).y); \
    fma2((ACCROW)[2], ad_, (B23).x); fma2((ACCROW)[3], ad_, (B23).y); } while(0)

// ---------- warp MMA / async helpers ----------
__device__ __forceinline__ uint32_t smem_u32(const void* p){
    uint32_t a;
    asm("{ .reg .u64 t; cvta.to.shared.u64 t, %1; cvt.u32.u64 %0, t; }" : "=r"(a) : "l"(p));
    return a;
}
__device__ __forceinline__ void cpa16(uint32_t smaddr, const void* g){
    asm volatile("cp.async.cg.shared.global [%0], [%1], 16;" :: "r"(smaddr), "l"(g));
}
#define CP_COMMIT() asm volatile("cp.async.commit_group;" ::: "memory")
#define CP_WAIT1()  asm volatile("cp.async.wait_group 1;" ::: "memory")
__device__ __forceinline__ void ldsm_x4(uint32_t &r0, uint32_t &r1, uint32_t &r2, uint32_t &r3, uint32_t addr){
    asm volatile("ldmatrix.sync.aligned.m8n8.x4.shared.b16 {%0,%1,%2,%3}, [%4];"
        : "=r"(r0), "=r"(r1), "=r"(r2), "=r"(r3) : "r"(addr));
}
__device__ __forceinline__ void ldsm_x2(uint32_t &r0, uint32_t &r1, uint32_t addr){
    asm volatile("ldmatrix.sync.aligned.m8n8.x2.shared.b16 {%0,%1}, [%2];"
        : "=r"(r0), "=r"(r1) : "r"(addr));
}
__device__ __forceinline__ void ldsm_x2t(uint32_t &r0, uint32_t &r1, uint32_t addr){
    asm volatile("ldmatrix.sync.aligned.m8n8.x2.trans.shared.b16 {%0,%1}, [%2];"
        : "=r"(r0), "=r"(r1) : "r"(addr));
}
__device__ __forceinline__ void mma16816(float &c0, float &c1, float &c2, float &c3,
                                         uint32_t a0, uint32_t a1, uint32_t a2, uint32_t a3,
                                         uint32_t b0, uint32_t b1){
    asm volatile("mma.sync.aligned.m16n8k16.row.col.f32.bf16.bf16.f32 "
        "{%0,%1,%2,%3}, {%4,%5,%6,%7}, {%8,%9}, {%0,%1,%2,%3};"
        : "+f"(c0), "+f"(c1), "+f"(c2), "+f"(c3)
        : "r"(a0), "r"(a1), "r"(a2), "r"(a3), "r"(b0), "r"(b1));
}
__device__ __forceinline__ uint32_t swu(int u, int r){ return (uint32_t)((u & 8) | ((u & 7) ^ (r & 7))); }
__device__ __forceinline__ uint32_t packh(float a, float b){
    __nv_bfloat162 t = __halves2bfloat162(__float2bfloat16_rn(a), __float2bfloat16_rn(b));
    return *(uint32_t*)&t;
}
__device__ __forceinline__ void bsplit2(__nv_bfloat16* H, __nv_bfloat16* L, size_t off, float2 v){
    __nv_bfloat16 hx = __float2bfloat16_rn(v.x), hy = __float2bfloat16_rn(v.y);
    __nv_bfloat16 lx = __float2bfloat16_rn(v.x - __bfloat162float(hx));
    __nv_bfloat16 ly = __float2bfloat16_rn(v.y - __bfloat162float(hy));
    *(__nv_bfloat162*)(H + off) = __halves2bfloat162(hx, hy);
    *(__nv_bfloat162*)(L + off) = __halves2bfloat162(lx, ly);
}
__device__ __forceinline__ float4 ld4hl(const __nv_bfloat16* H, const __nv_bfloat16* L, size_t off){
    uint2 h = *(const uint2*)(H + off), l = *(const uint2*)(L + off);
    float2 fh0 = __bfloat1622float2(*(__nv_bfloat162*)&h.x);
    float2 fh1 = __bfloat1622float2(*(__nv_bfloat162*)&h.y);
    float2 fl0 = __bfloat1622float2(*(__nv_bfloat162*)&l.x);
    float2 fl1 = __bfloat1622float2(*(__nv_bfloat162*)&l.y);
    return make_float4(fh0.x + fl0.x, fh0.y + fl0.y, fh1.x + fl1.x, fh1.y + fl1.y);
}

// ---------- dims: B=4, S=8192, D=1024, H=8, dk=dv=128, SEG=512, nseg=16 ----------

// ---------- device scratch ----------
__device__ float g_P[8388608];
__device__ float g_Zseg[65536];
__device__ float g_Z[65536];
__device__ __nv_bfloat16 g_Xh[33554432];
__device__ __nv_bfloat16 g_Xl[33554432];
__device__ __nv_bfloat16 g_Wth[3145728];
__device__ __nv_bfloat16 g_Wtl[3145728];
__device__ __nv_bfloat16 g_Qh[33554432];
__device__ __nv_bfloat16 g_Ql[33554432];
__device__ __nv_bfloat16 g_Kh[33554432];
__device__ __nv_bfloat16 g_Kl[33554432];
__device__ __nv_bfloat16 g_Vh[33554432];
__device__ __nv_bfloat16 g_Vl[33554432];
__device__ __nv_bfloat16 g_Memh[8388608];
__device__ __nv_bfloat16 g_Meml[8388608];

// =====================================================================
// S1: split X into bf16 hi/lo
// =====================================================================
__global__ __launch_bounds__(256) void k_splitX(const float* __restrict__ x)
{
    size_t i = ((size_t)blockIdx.x * 256 + threadIdx.x) * 4;
    float4 v = *(const float4*)(x + i);
    bsplit2(g_Xh, g_Xl, i,     make_float2(v.x, v.y));
    bsplit2(g_Xh, g_Xl, i + 2, make_float2(v.z, v.w));
}

// =====================================================================
// S2: transpose + split W[k][n] -> Wt[n][k] bf16 hi/lo
// =====================================================================
__global__ __launch_bounds__(256) void k_splitW(const float* __restrict__ w, int which)
{
    __shared__ float t[32][33];
    const int bx = blockIdx.x << 5, by = blockIdx.y << 5;
    const int tx = threadIdx.x & 31, ty = threadIdx.x >> 5;
#pragma unroll
    for (int r = 0; r < 4; ++r)
        t[ty * 4 + r][tx] = w[(size_t)(by + ty * 4 + r) * 1024 + bx + tx];
    __syncthreads();
    __nv_bfloat16* Ht = g_Wth + (size_t)which * 1048576;
    __nv_bfloat16* Lt = g_Wtl + (size_t)which * 1048576;
#pragma unroll
    for (int r = 0; r < 4; ++r) {
        int n = bx + ty * 4 + r, k = by + tx;
        float val = t[tx][ty * 4 + r];
        __nv_bfloat16 h = __float2bfloat16_rn(val);
        __nv_bfloat16 l = __float2bfloat16_rn(val - __bfloat162float(h));
        Ht[(size_t)n * 1024 + k] = h;
        Lt[(size_t)n * 1024 + k] = l;
    }
}

// =====================================================================
// K1: fused projection GEMM (grid.z = which). 512 threads, 16 warps
//     (4x4, warp tile 32x32). cp.async 3-stage pipeline, 1 sync/chunk,
//     pass-separated mma ordering for accumulator reuse distance.
// =====================================================================
__global__ __launch_bounds__(512, 1) void k_proj_mma(const float* __restrict__ bq,
                                                     const float* __restrict__ bk,
                                                     const float* __restrict__ bv)
{
    extern __shared__ __align__(128) char sm_raw[];
    const uint32_t smbase = smem_u32(sm_raw);

    const int which = blockIdx.z;
    const float* bias = (which == 0) ? bq : ((which == 1) ? bk : bv);
    __nv_bfloat16* Hd = (which == 0) ? g_Qh : ((which == 1) ? g_Kh : g_Vh);
    __nv_bfloat16* Ld = (which == 0) ? g_Ql : ((which == 1) ? g_Kl : g_Vl);
    const __nv_bfloat16* Wh = g_Wth + (size_t)which * 1048576;
    const __nv_bfloat16* Wl = g_Wtl + (size_t)which * 1048576;

    const int tid = threadIdx.x, lane = tid & 31, wid = tid >> 5;
    const int wm = (wid >> 2) * 32, wn = (wid & 3) * 32;
    const int row0 = blockIdx.y << 7, col0 = blockIdx.x << 7;

    const int rowA = wm + (lane & 15);
    const int rA7 = rowA & 7;
    const int unA = lane >> 4;
    const int rowB = wn + (lane & 7);
    const int rB7 = lane & 7;
    const int unB = (lane >> 3) & 1;

    // loader: 512 threads, per tile 2 x 16B per thread
    const int lr = tid >> 3, lu = tid & 7;   // r = lr + it*64, unit lu

    float cf[2][4][4];
#pragma unroll
    for (int mt = 0; mt < 2; ++mt)
#pragma unroll
        for (int nt = 0; nt < 4; ++nt)
#pragma unroll
            for (int q = 0; q < 4; ++q) cf[mt][nt][q] = 0.f;

    auto load_chunk = [&](int c, int stage) {
        const int k0 = c << 6;
        const uint32_t st = smbase + stage * 65536;
#pragma unroll
        for (int it = 0; it < 2; ++it) {
            int r = lr + it * 64;
            size_t ga = (size_t)(row0 + r) * 1024 + k0 + lu * 8;
            size_t gb = (size_t)(col0 + r) * 1024 + k0 + lu * 8;
            uint32_t so = r * 128 + ((lu ^ (r & 7)) << 4);
            cpa16(st + so,         g_Xh + ga);
            cpa16(st + 16384 + so, g_Xl + ga);
            cpa16(st + 32768 + so, Wh + gb);
            cpa16(st + 49152 + so, Wl + gb);
        }
    };

    load_chunk(0, 0); CP_COMMIT();
    load_chunk(1, 1); CP_COMMIT();

    for (int c = 0; c < 16; ++c) {
        CP_WAIT1();
        __syncthreads();
        if (c + 2 < 16) load_chunk(c + 2, (c + 2) % 3);
        CP_COMMIT();
        const uint32_t st = smbase + (c % 3) * 65536;
#pragma unroll
        for (int ks = 0; ks < 4; ++ks) {
            uint32_t ah[2][4], al[2][4], bh[4][2], bl[4][2];
#pragma unroll
            for (int mt = 0; mt < 2; ++mt) {
                uint32_t off = (rowA + mt * 16) * 128 + ((((ks << 1) + unA) ^ rA7) << 4);
                ldsm_x4(ah[mt][0], ah[mt][1], ah[mt][2], ah[mt][3], st + off);
                ldsm_x4(al[mt][0], al[mt][1], al[mt][2], al[mt][3], st + 16384 + off);
            }
#pragma unroll
            for (int nt = 0; nt < 4; ++nt) {
                uint32_t off = (rowB + nt * 8) * 128 + ((((ks << 1) + unB) ^ rB7) << 4);
                ldsm_x2(bh[nt][0], bh[nt][1], st + 32768 + off);
                ldsm_x2(bl[nt][0], bl[nt][1], st + 49152 + off);
            }
            // pass-separated: accumulator reuse distance = 8 mmas
#pragma unroll
            for (int nt = 0; nt < 4; ++nt)
#pragma unroll
                for (int mt = 0; mt < 2; ++mt)
                    mma16816(cf[mt][nt][0], cf[mt][nt][1], cf[mt][nt][2], cf[mt][nt][3],
                             ah[mt][0], ah[mt][1], ah[mt][2], ah[mt][3], bh[nt][0], bh[nt][1]);
#pragma unroll
            for (int nt = 0; nt < 4; ++nt)
#pragma unroll
                for (int mt = 0; mt < 2; ++mt)
                    mma16816(cf[mt][nt][0], cf[mt][nt][1], cf[mt][nt][2], cf[mt][nt][3],
                             ah[mt][0], ah[mt][1], ah[mt][2], ah[mt][3], bl[nt][0], bl[nt][1]);
#pragma unroll
            for (int nt = 0; nt < 4; ++nt)
#pragma unroll
                for (int mt = 0; mt < 2; ++mt)
                    mma16816(cf[mt][nt][0], cf[mt][nt][1], cf[mt][nt][2], cf[mt][nt][3],
                             al[mt][0], al[mt][1], al[mt][2], al[mt][3], bh[nt][0], bh[nt][1]);
        }
    }

    // epilogue: bias + bf16 hi/lo splits
#pragma unroll
    for (int mt = 0; mt < 2; ++mt) {
        const int r0 = row0 + wm + mt * 16 + (lane >> 2);
#pragma unroll
        for (int nt = 0; nt < 4; ++nt) {
            const int ccol = col0 + wn + nt * 8 + ((lane & 3) << 1);
            const float2 bvv = *(const float2*)&bias[ccol];
            float2 v0 = make_float2(cf[mt][nt][0] + bvv.x, cf[mt][nt][1] + bvv.y);
            float2 v1 = make_float2(cf[mt][nt][2] + bvv.x, cf[mt][nt][3] + bvv.y);
            size_t o0 = (size_t)r0 * 1024 + ccol;
            size_t o1 = o0 + 8 * 1024;
            bsplit2(Hd, Ld, o0, v0);
            bsplit2(Hd, Ld, o1, v1);
        }
    }
}

// =====================================================================
// K2: per (b,h,seg): P = (elu(K)+1)^T @ V  [128x128], Zseg = 512*colsum
// =====================================================================
__global__ __launch_bounds__(256) void k_kvouter()
{
    const int idx = blockIdx.x;
    const int b = idx >> 7, h = (idx >> 4) & 7, seg = idx & 15;
    __shared__ __align__(16) float sks[16][128];
    __shared__ __align__(16) float vvs[16][128];
    const int tid = threadIdx.x, tx = tid & 15, ty = tid >> 4;
    const int lr = tid >> 5, c4 = (tid & 31) << 2;

    ull_t acc[8][4];
#pragma unroll
    for (int i = 0; i < 8; ++i)
#pragma unroll
        for (int j = 0; j < 4; ++j) acc[i][j] = 0ull;
    float zacc[8] = {0.f,0.f,0.f,0.f,0.f,0.f,0.f,0.f};

    const size_t rowbase = (size_t)(b * 8192 + seg * 512) * 1024 + h * 128;

    for (int l0 = 0; l0 < 512; l0 += 16) {
        float4 k0v = ld4hl(g_Kh, g_Kl, rowbase + (size_t)(l0 + lr) * 1024 + c4);
        float4 k1v = ld4hl(g_Kh, g_Kl, rowbase + (size_t)(l0 + lr + 8) * 1024 + c4);
        float4 v0v = ld4hl(g_Vh, g_Vl, rowbase + (size_t)(l0 + lr) * 1024 + c4);
        float4 v1v = ld4hl(g_Vh, g_Vl, rowbase + (size_t)(l0 + lr + 8) * 1024 + c4);
        k0v.x = elup1(k0v.x); k0v.y = elup1(k0v.y); k0v.z = elup1(k0v.z); k0v.w = elup1(k0v.w);
        k1v.x = elup1(k1v.x); k1v.y = elup1(k1v.y); k1v.z = elup1(k1v.z); k1v.w = elup1(k1v.w);
        __syncthreads();
        *(float4*)&sks[lr][c4]     = k0v;
        *(float4*)&sks[lr + 8][c4] = k1v;
        *(float4*)&vvs[lr][c4]     = v0v;
        *(float4*)&vvs[lr + 8][c4] = v1v;
        __syncthreads();
#pragma unroll
        for (int l = 0; l < 16; ++l) {
            float4 a0 = *(const float4*)&sks[l][ty * 8];
            float4 a1 = *(const float4*)&sks[l][ty * 8 + 4];
            ulonglong2 b01 = *(const ulonglong2*)&vvs[l][tx * 8];
            ulonglong2 b23 = *(const ulonglong2*)&vvs[l][tx * 8 + 4];
            if (tx == 0) {
                zacc[0] += a0.x; zacc[1] += a0.y; zacc[2] += a0.z; zacc[3] += a0.w;
                zacc[4] += a1.x; zacc[5] += a1.y; zacc[6] += a1.z; zacc[7] += a1.w;
            }
            FMA8x4(acc[0], a0.x, b01, b23);
            FMA8x4(acc[1], a0.y, b01, b23);
            FMA8x4(acc[2], a0.z, b01, b23);
            FMA8x4(acc[3], a0.w, b01, b23);
            FMA8x4(acc[4], a1.x, b01, b23);
            FMA8x4(acc[5], a1.y, b01, b23);
            FMA8x4(acc[6], a1.z, b01, b23);
            FMA8x4(acc[7], a1.w, b01, b23);
        }
    }
    const size_t pbase = (size_t)idx * 16384;
#pragma unroll
    for (int i = 0; i < 8; ++i) {
        size_t rb = pbase + (size_t)(ty * 8 + i) * 128 + tx * 8;
#pragma unroll
        for (int jp = 0; jp < 4; ++jp) {
            float2 v = upk2(acc[i][jp]);
            g_P[rb + jp * 2]     = v.x;
            g_P[rb + jp * 2 + 1] = v.y;
        }
    }
    if (tx == 0) {
#pragma unroll
        for (int i = 0; i < 8; ++i)
            g_Zseg[idx * 128 + ty * 8 + i] = 512.f * zacc[i];
    }
}

// =====================================================================
// K3: inclusive prefix over seg; writes bf16 hi/lo Mem splits + Z
// =====================================================================
__global__ __launch_bounds__(256) void k_prefix()
{
    const int bh = blockIdx.x;
    const int tid = threadIdx.x;
    float acc[64];
#pragma unroll
    for (int u = 0; u < 64; ++u) acc[u] = 0.f;
    float zacc = 0.f;
    for (int seg = 0; seg < 16; ++seg) {
        const size_t base = ((size_t)bh * 16 + seg) * 16384;
#pragma unroll
        for (int u = 0; u < 64; ++u) {
            acc[u] += g_P[base + u * 256 + tid];
            float v = acc[u];
            __nv_bfloat16 h = __float2bfloat16_rn(v);
            __nv_bfloat16 l = __float2bfloat16_rn(v - __bfloat162float(h));
            g_Memh[base + u * 256 + tid] = h;
            g_Meml[base + u * 256 + tid] = l;
        }
        if (tid < 128) {
            zacc += g_Zseg[(bh * 16 + seg) * 128 + tid];
            g_Z[(bh * 16 + seg) * 128 + tid] = zacc;
        }
    }
}

// =====================================================================
// K4: mma.sync attention. CTA=(b,seg,qt64), 8 warps, loops 8 heads.
// =====================================================================
__global__ __launch_bounds__(256, 1) void k_attn_mma(const float* __restrict__ beta,
                                                     float* __restrict__ out)
{
    extern __shared__ __align__(16) char smraw[];
    float* Sc = (float*)smraw;                       // 132096 B
    char* sAh = smraw + 132096;                      // 16384
    char* sAl = sAh + 16384;                         // 16384
    char* sBh = sAl + 16384;                         // 32768
    char* sBl = sBh + 32768;                         // 32768
    float* zs  = (float*)(sBl + 32768);              // 128
    float* rs  = zs + 128;                           // 64
    float* den = rs + 64;                            // 64
    const uint32_t aAh = smem_u32(sAh), aAl = smem_u32(sAl);
    const uint32_t aBh = smem_u32(sBh), aBl = smem_u32(sBl);

    const int idx = blockIdx.x;                      // b*128 + seg*8 + qt
    const int b = idx >> 7, seg = (idx >> 3) & 15, qt = idx & 7;
    const int tid = threadIdx.x, lane = tid & 31, wid = tid >> 5;
    const int wm2 = (wid >> 2) * 32, wn2 = (wid & 3) * 32;
    const int qrow0 = b * 8192 + seg * 512 + qt * 64;
    const int krow0 = b * 8192 + seg * 512;
    const float bsig = 1.f / (1.f + __expf(-beta[0]));
    const float bsig8 = bsig * 0.125f, obsig8 = (1.f - bsig) * 0.125f;
    const float scale = 0.088388347648318447f;

    const int rowA0 = wm2 + (lane & 15);
    const int unA = lane >> 4;
    const int rowBn = wn2 + (lane & 7);
    const int unB = (lane >> 3) & 1;
    const int rowKt = (lane & 7) + ((lane >> 3) & 1) * 8;
    const int srow = tid >> 2, spart = tid & 3;

    float facc[2][4][4];
#pragma unroll
    for (int mt = 0; mt < 2; ++mt)
#pragma unroll
        for (int nt = 0; nt < 4; ++nt)
#pragma unroll
            for (int q = 0; q < 4; ++q) facc[mt][nt][q] = 0.f;

    for (int h = 0; h < 8; ++h) {
        const int hc = h * 128;
        __syncthreads();
#pragma unroll
        for (int it = 0; it < 4; ++it) {
            int i2 = it * 256 + tid;
            int r = i2 >> 4, u = i2 & 15;
            size_t gs = (size_t)(qrow0 + r) * 1024 + hc + u * 8;
            uint32_t so = r * 256 + (swu(u, r) << 4);
            *(uint4*)(sAh + so) = *(const uint4*)(g_Qh + gs);
            *(uint4*)(sAl + so) = *(const uint4*)(g_Ql + gs);
        }
        if (tid < 128)
            zs[tid] = g_Z[((size_t)(b * 8 + h) * 16 + seg) * 128 + tid];

        // ---- scores: 4 key chunks of 128 ----
        for (int kc = 0; kc < 4; ++kc) {
            __syncthreads();
#pragma unroll
            for (int it = 0; it < 8; ++it) {
                int i2 = it * 256 + tid;
                int r = i2 >> 4, u = i2 & 15;
                size_t gs = (size_t)(krow0 + kc * 128 + r) * 1024 + hc + u * 8;
                uint32_t so = r * 256 + (swu(u, r) << 4);
                *(uint4*)(sBh + so) = *(const uint4*)(g_Kh + gs);
                *(uint4*)(sBl + so) = *(const uint4*)(g_Kl + gs);
            }
            __syncthreads();
            float acc[2][4][4];
#pragma unroll
            for (int mt = 0; mt < 2; ++mt)
#pragma unroll
                for (int nt = 0; nt < 4; ++nt)
#pragma unroll
                    for (int q = 0; q < 4; ++q) acc[mt][nt][q] = 0.f;
            for (int pass = 0; pass < 3; ++pass) {
                const uint32_t Ab = (pass < 2) ? aAh : aAl;
                const uint32_t Bb = (pass == 1) ? aBl : aBh;
#pragma unroll
                for (int ks = 0; ks < 8; ++ks) {
                    uint32_t af[2][4], bfr[4][2];
#pragma unroll
                    for (int mt = 0; mt < 2; ++mt)
                        ldsm_x4(af[mt][0], af[mt][1], af[mt][2], af[mt][3],
                                Ab + (rowA0 + mt * 16) * 256 + (swu(ks * 2 + unA, rowA0) << 4));
#pragma unroll
                    for (int nt = 0; nt < 4; ++nt)
                        ldsm_x2(bfr[nt][0], bfr[nt][1],
                                Bb + (rowBn + nt * 8) * 256 + (swu(ks * 2 + unB, rowBn) << 4));
#pragma unroll
                    for (int nt = 0; nt < 4; ++nt)
#pragma unroll
                        for (int mt = 0; mt < 2; ++mt)
                            mma16816(acc[mt][nt][0], acc[mt][nt][1], acc[mt][nt][2], acc[mt][nt][3],
                                     af[mt][0], af[mt][1], af[mt][2], af[mt][3],
                                     bfr[nt][0], bfr[nt][1]);
                }
            }
#pragma unroll
            for (int mt = 0; mt < 2; ++mt) {
                int r0 = wm2 + mt * 16 + (lane >> 2);
#pragma unroll
                for (int nt = 0; nt < 4; ++nt) {
                    int cc = kc * 128 + wn2 + nt * 8 + ((lane & 3) << 1);
                    *(float2*)&Sc[r0 * 516 + cc]       = make_float2(acc[mt][nt][0] * scale, acc[mt][nt][1] * scale);
                    *(float2*)&Sc[(r0 + 8) * 516 + cc] = make_float2(acc[mt][nt][2] * scale, acc[mt][nt][3] * scale);
                }
            }
        }
        __syncthreads();
        // ---- softmax ----
        {
            float* rowp = &Sc[srow * 516 + spart * 128];
            float m = -1e30f;
#pragma unroll 8
            for (int j = 0; j < 128; ++j) m = fmaxf(m, rowp[j]);
            m = fmaxf(m, __shfl_xor_sync(0xffffffffu, m, 1));
            m = fmaxf(m, __shfl_xor_sync(0xffffffffu, m, 2));
            float s = 0.f;
#pragma unroll 8
            for (int j = 0; j < 128; ++j) { float e = __expf(rowp[j] - m); rowp[j] = e; s += e; }
            s += __shfl_xor_sync(0xffffffffu, s, 1);
            s += __shfl_xor_sync(0xffffffffu, s, 2);
            if (spart == 0) rs[srow] = s;
        }
        // ---- sq transform + exact den ----
        {
            float da = 0.f;
#pragma unroll 4
            for (int j = 0; j < 32; ++j) {
                int c = spart * 32 + j;
                uint32_t bo = srow * 256 + (swu(c >> 3, srow) << 4) + ((c & 7) << 1);
                float qh = __bfloat162float(*(__nv_bfloat16*)(sAh + bo));
                float ql = __bfloat162float(*(__nv_bfloat16*)(sAl + bo));
                float sq = elup1(qh + ql);
                da += sq * zs[c];
                __nv_bfloat16 hh = __float2bfloat16_rn(sq);
                __nv_bfloat16 ll = __float2bfloat16_rn(sq - __bfloat162float(hh));
                *(__nv_bfloat16*)(sAh + bo) = hh;
                *(__nv_bfloat16*)(sAl + bo) = ll;
            }
            da += __shfl_xor_sync(0xffffffffu, da, 1);
            da += __shfl_xor_sync(0xffffffffu, da, 2);
            if (spart == 0) den[srow] = da;
        }
        __syncthreads();
        // ---- retrieval ----
#pragma unroll
        for (int it = 0; it < 8; ++it) {
            int i2 = it * 256 + tid;
            int r = i2 >> 4, u = i2 & 15;
            size_t ms = ((size_t)(b * 8 + h) * 16 + seg) * 16384 + r * 128 + u * 8;
            uint32_t so = r * 256 + (swu(u, r) << 4);
            *(uint4*)(sBh + so) = *(const uint4*)(g_Memh + ms);
            *(uint4*)(sBl + so) = *(const uint4*)(g_Meml + ms);
        }
        __syncthreads();
        {
            float acc[2][4][4];
#pragma unroll
            for (int mt = 0; mt < 2; ++mt)
#pragma unroll
                for (int nt = 0; nt < 4; ++nt)
#pragma unroll
                    for (int q = 0; q < 4; ++q) acc[mt][nt][q] = 0.f;
            for (int pass = 0; pass < 3; ++pass) {
                const uint32_t Ab = (pass < 2) ? aAh : aAl;
                const uint32_t Bb = (pass == 1) ? aBl : aBh;
#pragma unroll
                for (int ks = 0; ks < 8; ++ks) {
                    uint32_t af[2][4], bfr[4][2];
#pragma unroll
                    for (int mt = 0; mt < 2; ++mt)
                        ldsm_x4(af[mt][0], af[mt][1], af[mt][2], af[mt][3],
                                Ab + (rowA0 + mt * 16) * 256 + (swu(ks * 2 + unA, rowA0) << 4));
                    int rK = ks * 16 + rowKt;
#pragma unroll
                    for (int nt = 0; nt < 4; ++nt)
                        ldsm_x2t(bfr[nt][0], bfr[nt][1],
                                 Bb + rK * 256 + (swu((wn2 >> 3) + nt, rK) << 4));
#pragma unroll
                    for (int nt = 0; nt < 4; ++nt)
#pragma unroll
                        for (int mt = 0; mt < 2; ++mt)
                            mma16816(acc[mt][nt][0], acc[mt][nt][1], acc[mt][nt][2], acc[mt][nt][3],
                                     af[mt][0], af[mt][1], af[mt][2], af[mt][3],
                                     bfr[nt][0], bfr[nt][1]);
                }
            }
#pragma unroll
            for (int mt = 0; mt < 2; ++mt) {
                int r0 = wm2 + mt * 16 + (lane >> 2);
                float m0 = bsig8 / (den[r0] + 1e-5f);
                float m1 = bsig8 / (den[r0 + 8] + 1e-5f);
#pragma unroll
                for (int nt = 0; nt < 4; ++nt) {
                    facc[mt][nt][0] += acc[mt][nt][0] * m0;
                    facc[mt][nt][1] += acc[mt][nt][1] * m0;
                    facc[mt][nt][2] += acc[mt][nt][2] * m1;
                    facc[mt][nt][3] += acc[mt][nt][3] * m1;
                }
            }
        }
        // ---- PV ----
        float dacc[2][4][4];
#pragma unroll
        for (int mt = 0; mt < 2; ++mt)
#pragma unroll
            for (int nt = 0; nt < 4; ++nt)
#pragma unroll
                for (int q = 0; q < 4; ++q) dacc[mt][nt][q] = 0.f;
        for (int kc = 0; kc < 4; ++kc) {
            __syncthreads();
#pragma unroll
            for (int it = 0; it < 4; ++it) {
                int i2 = it * 256 + tid;
                int r = i2 >> 4, u = i2 & 15;
                const float* sp = &Sc[r * 516 + kc * 128 + u * 8];
                float4 p0 = *(const float4*)sp, p1 = *(const float4*)(sp + 4);
                uint4 hi, lo;
                hi.x = packh(p0.x, p0.y); hi.y = packh(p0.z, p0.w);
                hi.z = packh(p1.x, p1.y); hi.w = packh(p1.z, p1.w);
                lo.x = packh(p0.x - __bfloat162float(__float2bfloat16_rn(p0.x)),
                             p0.y - __bfloat162float(__float2bfloat16_rn(p0.y)));
                lo.y = packh(p0.z - __bfloat162float(__float2bfloat16_rn(p0.z)),
                             p0.w - __bfloat162float(__float2bfloat16_rn(p0.w)));
                lo.z = packh(p1.x - __bfloat162float(__float2bfloat16_rn(p1.x)),
                             p1.y - __bfloat162float(__float2bfloat16_rn(p1.y)));
                lo.w = packh(p1.z - __bfloat162float(__float2bfloat16_rn(p1.z)),
                             p1.w - __bfloat162float(__float2bfloat16_rn(p1.w)));
                uint32_t so = r * 256 + (swu(u, r) << 4);
                *(uint4*)(sAh + so) = hi;
                *(uint4*)(sAl + so) = lo;
            }
#pragma unroll
            for (int it = 0; it < 8; ++it) {
                int i2 = it * 256 + tid;
                int r = i2 >> 4, u = i2 & 15;
                size_t gs = (size_t)(krow0 + kc * 128 + r) * 1024 + hc + u * 8;
                uint32_t so = r * 256 + (swu(u, r) << 4);
                *(uint4*)(sBh + so) = *(const uint4*)(g_Vh + gs);
                *(uint4*)(sBl + so) = *(const uint4*)(g_Vl + gs);
            }
            __syncthreads();
            for (int pass = 0; pass < 3; ++pass) {
                const uint32_t Ab = (pass < 2) ? aAh : aAl;
                const uint32_t Bb = (pass == 1) ? aBl : aBh;
#pragma unroll
                for (int ks = 0; ks < 8; ++ks) {
                    uint32_t af[2][4], bfr[4][2];
#pragma unroll
                    for (int mt = 0; mt < 2; ++mt)
                        ldsm_x4(af[mt][0], af[mt][1], af[mt][2], af[mt][3],
                                Ab + (rowA0 + mt * 16) * 256 + (swu(ks * 2 + unA, rowA0) << 4));
                    int rK = ks * 16 + rowKt;
#pragma unroll
                    for (int nt = 0; nt < 4; ++nt)
                        ldsm_x2t(bfr[nt][0], bfr[nt][1],
                                 Bb + rK * 256 + (swu((wn2 >> 3) + nt, rK) << 4));
#pragma unroll
                    for (int nt = 0; nt < 4; ++nt)
#pragma unroll
                        for (int mt = 0; mt < 2; ++mt)
                            mma16816(dacc[mt][nt][0], dacc[mt][nt][1], dacc[mt][nt][2], dacc[mt][nt][3],
                                     af[mt][0], af[mt][1], af[mt][2], af[mt][3],
                                     bfr[nt][0], bfr[nt][1]);
                }
            }
        }
#pragma unroll
        for (int mt = 0; mt < 2; ++mt) {
            int r0 = wm2 + mt * 16 + (lane >> 2);
            float d0 = obsig8 / rs[r0];
            float d1 = obsig8 / rs[r0 + 8];
#pragma unroll
            for (int nt = 0; nt < 4; ++nt) {
                facc[mt][nt][0] += dacc[mt][nt][0] * d0;
                facc[mt][nt][1] += dacc[mt][nt][1] * d0;
                facc[mt][nt][2] += dacc[mt][nt][2] * d1;
                facc[mt][nt][3] += dacc[mt][nt][3] * d1;
            }
        }
    }

#pragma unroll
    for (int mt = 0; mt < 2; ++mt) {
        int r0 = wm2 + mt * 16 + (lane >> 2);
#pragma unroll
        for (int nt = 0; nt < 4; ++nt) {
            int col = wn2 + nt * 8 + ((lane & 3) << 1);
            *(float2*)&out[(size_t)(qrow0 + r0) * 128 + col]     = make_float2(facc[mt][nt][0], facc[mt][nt][1]);
            *(float2*)&out[(size_t)(qrow0 + r0 + 8) * 128 + col] = make_float2(facc[mt][nt][2], facc[mt][nt][3]);
        }
    }
}

// =====================================================================
extern "C" void kernel_launch(void* const* d_in, const int* in_sizes, int n_in,
                              void* d_out, int out_size)
{
    const float* x    = (const float*)d_in[0];
    const float* wq   = (const float*)d_in[1];
    const float* bq   = (const float*)d_in[2];
    const float* wk   = (const float*)d_in[3];
    const float* bk   = (const float*)d_in[4];
    const float* wv   = (const float*)d_in[5];
    const float* bv   = (const float*)d_in[6];
    const float* beta = (const float*)d_in[7];
    float* out = (float*)d_out;

    static int attr_set = 0;
    if (!attr_set) {
        cudaFuncSetAttribute(k_attn_mma, cudaFuncAttributeMaxDynamicSharedMemorySize, 231424);
        cudaFuncSetAttribute(k_proj_mma, cudaFuncAttributeMaxDynamicSharedMemorySize, 196608);
        attr_set = 1;
    }

    k_splitX<<<32768, 256>>>(x);
    k_splitW<<<dim3(32, 32), 256>>>(wq, 0);
    k_splitW<<<dim3(32, 32), 256>>>(wk, 1);
    k_splitW<<<dim3(32, 32), 256>>>(wv, 2);
    k_proj_mma<<<dim3(8, 256, 3), 512, 196608>>>(bq, bk, bv);
    k_kvouter<<<512, 256>>>();
    k_prefix<<<32, 256>>>();
    k_attn_mma<<<512, 256, 231424>>>(beta, out);
}